// round 2
// baseline (speedup 1.0000x reference)
#include <cuda_runtime.h>
#include <math.h>

#define DD 1024
#define HEADS 16
#define DH 64
#define B_LAT 9
#define B_X 8
#define N_KV 256
#define N_Q 64
#define KV_PER_B (N_KV + N_Q)       /* 320  */
#define ROWS_X (B_X * N_KV)         /* 2048 */
#define ROWS_LAT (B_LAT * N_Q)      /* 576  */
#define ROWS_KV (B_X * KV_PER_B)    /* 2560 */
#define EPS 1e-5f

// ---------------- scratch (static device globals; no allocation) ----------------
__device__ float g_kvin[ROWS_KV * DD];       // LN(x) ++ LN(latents[:-1]) in concat layout
__device__ float g_lnlat[ROWS_LAT * DD];     // LN(latents), all 9 batches
__device__ float g_q[ROWS_LAT * DD];         // Q = lnlat @ Wq   (row q, col h*64+d)
__device__ float g_kv[ROWS_KV * 2 * DD];     // [K | V] = kvin @ Wkv
__device__ float g_ao[ROWS_LAT * DD];        // attention out, (q, h*64+d) layout

// ---------------- LayerNorm: one block per row, 256 threads ----------------
__global__ void ln_kernel(const float* __restrict__ x, const float* __restrict__ lat,
                          const float* __restrict__ g1, const float* __restrict__ b1,
                          const float* __restrict__ g2, const float* __restrict__ b2) {
    int row = blockIdx.x;
    const float *src, *g, *b;
    float *dst0, *dst1 = nullptr;
    if (row < ROWS_X) {
        int bb = row / N_KV, n = row % N_KV;
        src = x + (size_t)row * DD; g = g1; b = b1;
        dst0 = g_kvin + (size_t)(bb * KV_PER_B + n) * DD;
    } else {
        int lr = row - ROWS_X;
        int bb = lr / N_Q, n = lr % N_Q;
        src = lat + (size_t)lr * DD; g = g2; b = b2;
        dst0 = g_lnlat + (size_t)lr * DD;
        if (bb < B_X) dst1 = g_kvin + (size_t)(bb * KV_PER_B + N_KV + n) * DD;
    }
    int tid = threadIdx.x;
    float4 v = ((const float4*)src)[tid];
    float s  = v.x + v.y + v.z + v.w;
    float ss = v.x*v.x + v.y*v.y + v.z*v.z + v.w*v.w;
    #pragma unroll
    for (int o = 16; o; o >>= 1) {
        s  += __shfl_xor_sync(0xFFFFFFFFu, s,  o);
        ss += __shfl_xor_sync(0xFFFFFFFFu, ss, o);
    }
    __shared__ float sb[8], ssb[8];
    int wid = tid >> 5, lane = tid & 31;
    if (lane == 0) { sb[wid] = s; ssb[wid] = ss; }
    __syncthreads();
    float ts = 0.f, tss = 0.f;
    #pragma unroll
    for (int i = 0; i < 8; i++) { ts += sb[i]; tss += ssb[i]; }
    float mean = ts * (1.0f / DD);
    float var  = tss * (1.0f / DD) - mean * mean;
    float inv  = rsqrtf(var + EPS);
    float4 gg = ((const float4*)g)[tid];
    float4 bb4 = ((const float4*)b)[tid];
    float4 o;
    o.x = (v.x - mean) * inv * gg.x + bb4.x;
    o.y = (v.y - mean) * inv * gg.y + bb4.y;
    o.z = (v.z - mean) * inv * gg.z + bb4.z;
    o.w = (v.w - mean) * inv * gg.w + bb4.w;
    ((float4*)dst0)[tid] = o;
    if (dst1) ((float4*)dst1)[tid] = o;
}

// ---------------- fp32 SGEMM: C[M,N] = A[M,K] @ B[K,N], 128x128x16 tiles ----------------
// Operand selection is compile-time (template) so no host symbol queries are needed.
#define BM 128
#define BN 128
#define BK 16

enum GemmOp { GEMM_Q = 0, GEMM_KV = 1, GEMM_OUT = 2 };

template <int OP>
__global__ __launch_bounds__(256, 2)
void sgemm(const float* __restrict__ W, float* __restrict__ Cext,
           int M, int N, int K) {
    const float* A = (OP == GEMM_Q)   ? g_lnlat
                   : (OP == GEMM_KV)  ? g_kvin
                                      : g_ao;
    float* C = (OP == GEMM_Q)  ? g_q
             : (OP == GEMM_KV) ? g_kv
                               : Cext;
    const float* B = W;

    __shared__ float As[BK][BM];
    __shared__ float Bs[BK][BN];
    int br = blockIdx.y * BM, bc = blockIdx.x * BN;
    int tid = threadIdx.x;
    int ty = tid / 16, tx = tid % 16;
    float acc[8][8] = {};
    for (int k0 = 0; k0 < K; k0 += BK) {
        #pragma unroll
        for (int i = tid; i < 512; i += 256) {
            int r = i >> 2, c4 = i & 3;
            float4 v;
            if (br + r < M) v = *(const float4*)&A[(size_t)(br + r) * K + k0 + c4 * 4];
            else            v = make_float4(0.f, 0.f, 0.f, 0.f);
            As[c4 * 4 + 0][r] = v.x; As[c4 * 4 + 1][r] = v.y;
            As[c4 * 4 + 2][r] = v.z; As[c4 * 4 + 3][r] = v.w;
        }
        #pragma unroll
        for (int i = tid; i < 512; i += 256) {
            int r = i >> 5, c4 = i & 31;
            *(float4*)&Bs[r][c4 * 4] = *(const float4*)&B[(size_t)(k0 + r) * N + bc + c4 * 4];
        }
        __syncthreads();
        #pragma unroll
        for (int kk = 0; kk < BK; kk++) {
            float a[8], bb[8];
            #pragma unroll
            for (int i = 0; i < 8; i++) a[i]  = As[kk][ty * 8 + i];
            #pragma unroll
            for (int j = 0; j < 8; j++) bb[j] = Bs[kk][tx * 8 + j];
            #pragma unroll
            for (int i = 0; i < 8; i++)
                #pragma unroll
                for (int j = 0; j < 8; j++) acc[i][j] += a[i] * bb[j];
        }
        __syncthreads();
    }
    #pragma unroll
    for (int i = 0; i < 8; i++) {
        int r = br + ty * 8 + i;
        if (r >= M) break;
        #pragma unroll
        for (int j4 = 0; j4 < 2; j4++) {
            float4 v = make_float4(acc[i][j4*4], acc[i][j4*4+1], acc[i][j4*4+2], acc[i][j4*4+3]);
            *(float4*)&C[(size_t)r * N + bc + tx * 8 + j4 * 4] = v;
        }
    }
}

// ---------------- attention: one block per (q row, head), two-pass softmax ----------------
// Mask is block-diagonal: q block qb<8 attends to keys [qb*320, qb*320+320);
// q block 8 attends to all 2560. exp(-FLT_MAX - m) == 0, so this is exact.
__global__ __launch_bounds__(128)
void attn_kernel(const int* __restrict__ use_mask_p) {
    int q = blockIdx.x;       // 0..575
    int h = blockIdx.y;       // 0..15
    int qb = q >> 6;
    int um = *use_mask_p;
    int k_start, k_count;
    if (um && qb < B_X) { k_start = qb * KV_PER_B; k_count = KV_PER_B; }
    else                { k_start = 0;             k_count = ROWS_KV; }

    __shared__ float qv[DH];
    __shared__ float sc[ROWS_KV];
    __shared__ float rbuf[4];

    int tid = threadIdx.x;
    const float* qrow = g_q + (size_t)q * DD + h * DH;
    if (tid < DH) qv[tid] = qrow[tid];
    __syncthreads();

    const float scale2 = 0.125f;  // DH^-0.5

    // pass 1: scores + local max
    float lmax = -INFINITY;
    for (int j = tid; j < k_count; j += 128) {
        const float4* k4 = (const float4*)(g_kv + (size_t)(k_start + j) * (2 * DD) + h * DH);
        const float4* q4 = (const float4*)qv;
        float s = 0.f;
        #pragma unroll
        for (int d4 = 0; d4 < 16; d4++) {
            float4 kk = k4[d4], qq = q4[d4];
            s += kk.x * qq.x + kk.y * qq.y + kk.z * qq.z + kk.w * qq.w;
        }
        s *= scale2;
        sc[j] = s;
        lmax = fmaxf(lmax, s);
    }
    #pragma unroll
    for (int o = 16; o; o >>= 1) lmax = fmaxf(lmax, __shfl_xor_sync(0xFFFFFFFFu, lmax, o));
    if ((tid & 31) == 0) rbuf[tid >> 5] = lmax;
    __syncthreads();
    float gmax = fmaxf(fmaxf(rbuf[0], rbuf[1]), fmaxf(rbuf[2], rbuf[3]));
    __syncthreads();

    // pass 2: exp + sum
    float lsum = 0.f;
    for (int j = tid; j < k_count; j += 128) {
        float p = __expf(sc[j] - gmax);
        sc[j] = p;
        lsum += p;
    }
    #pragma unroll
    for (int o = 16; o; o >>= 1) lsum += __shfl_xor_sync(0xFFFFFFFFu, lsum, o);
    if ((tid & 31) == 0) rbuf[tid >> 5] = lsum;
    __syncthreads();
    float inv = 1.0f / (rbuf[0] + rbuf[1] + rbuf[2] + rbuf[3]);

    // pass 3: O = P @ V. Each warp owns a 16-wide d-slice; lanes split into
    // 2 key-stripes of 16 d-values... simpler: thread -> (stripe, d) with
    // stripe = tid>>6 in {0,1}, d = tid&63; accumulate independently, then
    // combine via shfl within pairs spaced 64 apart using shared memory once.
    int d = tid & 63, stripe = tid >> 6;
    float o = 0.f;
    for (int j = stripe; j < k_count; j += 2)
        o += sc[j] * g_kv[(size_t)(k_start + j) * (2 * DD) + DD + h * DH + d];
    __shared__ float opart[DH];
    if (stripe == 0) opart[d] = o;
    __syncthreads();
    if (stripe == 1) g_ao[(size_t)q * DD + h * DH + d] = (opart[d] + o) * inv;
}

// ---------------- launch ----------------
extern "C" void kernel_launch(void* const* d_in, const int* in_sizes, int n_in,
                              void* d_out, int out_size) {
    const float* x    = (const float*)d_in[0];
    const float* lat  = (const float*)d_in[1];
    const float* g1   = (const float*)d_in[2];
    const float* b1   = (const float*)d_in[3];
    const float* g2   = (const float*)d_in[4];
    const float* b2   = (const float*)d_in[5];
    const float* Wq   = (const float*)d_in[6];
    const float* Wkv  = (const float*)d_in[7];
    const float* Wout = (const float*)d_in[8];
    const int*   um   = (const int*)d_in[9];
    float* out = (float*)d_out;

    // 1. LayerNorms (x -> kvin[:,0:256], latents -> lnlat and kvin[:,256:320])
    ln_kernel<<<ROWS_X + ROWS_LAT, 256>>>(x, lat, g1, b1, g2, b2);

    // 2. Q = lnlat @ Wq           (576 x 1024 x 1024)
    sgemm<GEMM_Q><<<dim3(DD / BN, (ROWS_LAT + BM - 1) / BM), 256>>>(Wq, nullptr, ROWS_LAT, DD, DD);

    // 3. KV = kvin @ Wkv          (2560 x 2048 x 1024)
    sgemm<GEMM_KV><<<dim3(2 * DD / BN, ROWS_KV / BM), 256>>>(Wkv, nullptr, ROWS_KV, 2 * DD, DD);

    // 4. masked attention
    attn_kernel<<<dim3(ROWS_LAT, HEADS), 128>>>(um);

    // 5. out = ao @ Wout          (576 x 1024 x 1024), straight into d_out
    sgemm<GEMM_OUT><<<dim3(DD / BN, (ROWS_LAT + BM - 1) / BM), 256>>>(Wout, out, ROWS_LAT, DD, DD);
}

// round 5
// speedup vs baseline: 1.5326x; 1.5326x over previous
#include <cuda_runtime.h>
#include <math.h>

#define DD 1024
#define HEADS 16
#define DH 64
#define B_LAT 9
#define B_X 8
#define N_KV 256
#define N_Q 64
#define KV_PER_B (N_KV + N_Q)       /* 320  */
#define ROWS_X (B_X * N_KV)         /* 2048 */
#define ROWS_LAT (B_LAT * N_Q)      /* 576  */
#define ROWS_KV (B_X * KV_PER_B)    /* 2560 */
#define EPS 1e-5f
#define NCHUNK 8                    /* 2560/320 */
#define NPART (B_LAT * HEADS * NCHUNK)   /* 1152 */

// ---------------- scratch (static device globals; no allocation) ----------------
__device__ float g_kvin[ROWS_KV * DD];
__device__ float g_lnlat[ROWS_LAT * DD];
__device__ float g_q[ROWS_LAT * DD];
__device__ float g_kv[ROWS_KV * 2 * DD];
__device__ float g_ao[ROWS_LAT * DD];
// split-KV partials: unnormalized O, running max m, running sum l
__device__ float g_pO[(size_t)NPART * 64 * 64];
__device__ float g_pm[NPART * 64];
__device__ float g_pl[NPART * 64];

// ---------------- LayerNorm: one block per row, 256 threads ----------------
__global__ void ln_kernel(const float* __restrict__ x, const float* __restrict__ lat,
                          const float* __restrict__ g1, const float* __restrict__ b1,
                          const float* __restrict__ g2, const float* __restrict__ b2) {
    int row = blockIdx.x;
    const float *src, *g, *b;
    float *dst0, *dst1 = nullptr;
    if (row < ROWS_X) {
        int bb = row / N_KV, n = row % N_KV;
        src = x + (size_t)row * DD; g = g1; b = b1;
        dst0 = g_kvin + (size_t)(bb * KV_PER_B + n) * DD;
    } else {
        int lr = row - ROWS_X;
        int bb = lr / N_Q, n = lr % N_Q;
        src = lat + (size_t)lr * DD; g = g2; b = b2;
        dst0 = g_lnlat + (size_t)lr * DD;
        if (bb < B_X) dst1 = g_kvin + (size_t)(bb * KV_PER_B + N_KV + n) * DD;
    }
    int tid = threadIdx.x;
    float4 v = ((const float4*)src)[tid];
    float s  = v.x + v.y + v.z + v.w;
    float ss = v.x*v.x + v.y*v.y + v.z*v.z + v.w*v.w;
    #pragma unroll
    for (int o = 16; o; o >>= 1) {
        s  += __shfl_xor_sync(0xFFFFFFFFu, s,  o);
        ss += __shfl_xor_sync(0xFFFFFFFFu, ss, o);
    }
    __shared__ float sb[8], ssb[8];
    int wid = tid >> 5, lane = tid & 31;
    if (lane == 0) { sb[wid] = s; ssb[wid] = ss; }
    __syncthreads();
    float ts = 0.f, tss = 0.f;
    #pragma unroll
    for (int i = 0; i < 8; i++) { ts += sb[i]; tss += ssb[i]; }
    float mean = ts * (1.0f / DD);
    float var  = tss * (1.0f / DD) - mean * mean;
    float inv  = rsqrtf(var + EPS);
    float4 gg = ((const float4*)g)[tid];
    float4 bb4 = ((const float4*)b)[tid];
    float4 o;
    o.x = (v.x - mean) * inv * gg.x + bb4.x;
    o.y = (v.y - mean) * inv * gg.y + bb4.y;
    o.z = (v.z - mean) * inv * gg.z + bb4.z;
    o.w = (v.w - mean) * inv * gg.w + bb4.w;
    ((float4*)dst0)[tid] = o;
    if (dst1) ((float4*)dst1)[tid] = o;
}

// ---------------- fp32 SGEMM: C[M,N] = A[M,K] @ B[K,N], 128x128x16 tiles ----------------
#define BM 128
#define BN 128
#define BK 16

enum GemmOp { GEMM_Q = 0, GEMM_KV = 1, GEMM_OUT = 2 };

template <int OP>
__global__ __launch_bounds__(256, 2)
void sgemm(const float* __restrict__ W, float* __restrict__ Cext,
           int M, int N, int K) {
    const float* A = (OP == GEMM_Q)   ? g_lnlat
                   : (OP == GEMM_KV)  ? g_kvin
                                      : g_ao;
    float* C = (OP == GEMM_Q)  ? g_q
             : (OP == GEMM_KV) ? g_kv
                               : Cext;
    const float* B = W;

    __shared__ float As[BK][BM];
    __shared__ float Bs[BK][BN];
    int br = blockIdx.y * BM, bc = blockIdx.x * BN;
    int tid = threadIdx.x;
    int ty = tid / 16, tx = tid % 16;
    float acc[8][8] = {};
    for (int k0 = 0; k0 < K; k0 += BK) {
        #pragma unroll
        for (int i = tid; i < 512; i += 256) {
            int r = i >> 2, c4 = i & 3;
            float4 v;
            if (br + r < M) v = *(const float4*)&A[(size_t)(br + r) * K + k0 + c4 * 4];
            else            v = make_float4(0.f, 0.f, 0.f, 0.f);
            As[c4 * 4 + 0][r] = v.x; As[c4 * 4 + 1][r] = v.y;
            As[c4 * 4 + 2][r] = v.z; As[c4 * 4 + 3][r] = v.w;
        }
        #pragma unroll
        for (int i = tid; i < 512; i += 256) {
            int r = i >> 5, c4 = i & 31;
            *(float4*)&Bs[r][c4 * 4] = *(const float4*)&B[(size_t)(k0 + r) * N + bc + c4 * 4];
        }
        __syncthreads();
        #pragma unroll
        for (int kk = 0; kk < BK; kk++) {
            float a[8], bb[8];
            #pragma unroll
            for (int i = 0; i < 8; i++) a[i]  = As[kk][ty * 8 + i];
            #pragma unroll
            for (int j = 0; j < 8; j++) bb[j] = Bs[kk][tx * 8 + j];
            #pragma unroll
            for (int i = 0; i < 8; i++)
                #pragma unroll
                for (int j = 0; j < 8; j++) acc[i][j] += a[i] * bb[j];
        }
        __syncthreads();
    }
    #pragma unroll
    for (int i = 0; i < 8; i++) {
        int r = br + ty * 8 + i;
        if (r >= M) break;
        #pragma unroll
        for (int j4 = 0; j4 < 2; j4++) {
            float4 v = make_float4(acc[i][j4*4], acc[i][j4*4+1], acc[i][j4*4+2], acc[i][j4*4+3]);
            *(float4*)&C[(size_t)r * N + bc + tx * 8 + j4 * 4] = v;
        }
    }
}

// ---------------- flash attention, query-tiled + split-KV, STATIC smem ----------------
// Block = (qb 0..8, h 0..15, chunk c 0..7): 64-query tile vs keys [c*320, c*320+320),
// streamed in 32-key subtiles. With use_mask, qb<8 handles only chunk qb (exact:
// exp(-FLT_MAX) == 0) and writes normalized output; qb==8 / unmasked path writes
// 8 partials merged by attn_combine.
#define QSTR 68   /* Qs/Vs row stride */
#define KSTR 36   /* Ks/Ps row stride */
#define KSUB 32

__global__ __launch_bounds__(256)
void attn_flash(const int* __restrict__ um_p) {
    int b  = blockIdx.x;
    int qb = b >> 7;
    int h  = (b >> 3) & 15;
    int c  = b & 7;
    int um = *um_p;
    bool single = (um != 0) && (qb < B_X);
    if (single && c != qb) return;    // whole block exits before any barrier

    __shared__ float Qs[64 * QSTR];   // [d][q], pre-scaled      17408 B
    __shared__ float Ks[64 * KSTR];   // [d][k]                   9216 B
    __shared__ float Vs[KSUB * QSTR]; // [k][d]                   8704 B
    __shared__ float Ps[64 * KSTR];   // [q][k] scores->probs     9216 B
    __shared__ float mrow[64], lrow[64], arow[64];             /* 768 B */

    int tid = threadIdx.x;
    int ty = tid >> 4, tx = tid & 15;   // ty: 4 q-rows; tx: k pairs / d quads

    // load Q tile transposed, scale DH^-0.5 folded in
    #pragma unroll
    for (int it = 0; it < 4; it++) {
        int row = ty + it * 16;
        int col = tx * 4;
        float4 v = *(const float4*)&g_q[(size_t)(qb * 64 + row) * DD + h * DH + col];
        Qs[(col + 0) * QSTR + row] = v.x * 0.125f;
        Qs[(col + 1) * QSTR + row] = v.y * 0.125f;
        Qs[(col + 2) * QSTR + row] = v.z * 0.125f;
        Qs[(col + 3) * QSTR + row] = v.w * 0.125f;
    }
    if (tid < 64) { mrow[tid] = -INFINITY; lrow[tid] = 0.f; }

    float oacc[4][4] = {};
    int ks0 = c * KV_PER_B;

    for (int sub = 0; sub < 10; sub++) {
        int kb = ks0 + sub * KSUB;
        __syncthreads();   // prior-iter reads done (and Qs/mrow init before iter 0)
        // K subtile (32 x 64) transposed + V subtile row-major: 2 float4 per thread
        {
            int r = tid >> 4;          // 0..15
            int c4 = (tid & 15) * 4;
            const float* base0 = g_kv + (size_t)(kb + r) * (2 * DD) + h * DH + c4;
            float4 kk = *(const float4*)base0;
            Ks[(c4 + 0) * KSTR + r] = kk.x;
            Ks[(c4 + 1) * KSTR + r] = kk.y;
            Ks[(c4 + 2) * KSTR + r] = kk.z;
            Ks[(c4 + 3) * KSTR + r] = kk.w;
            *(float4*)&Vs[r * QSTR + c4] = *(const float4*)(base0 + DD);
            int r2 = r + 16;
            const float* base1 = g_kv + (size_t)(kb + r2) * (2 * DD) + h * DH + c4;
            float4 k2 = *(const float4*)base1;
            Ks[(c4 + 0) * KSTR + r2] = k2.x;
            Ks[(c4 + 1) * KSTR + r2] = k2.y;
            Ks[(c4 + 2) * KSTR + r2] = k2.z;
            Ks[(c4 + 3) * KSTR + r2] = k2.w;
            *(float4*)&Vs[r2 * QSTR + c4] = *(const float4*)(base1 + DD);
        }
        __syncthreads();

        // S = Q K^T : thread computes 4q x 2k
        float sacc[4][2] = {};
        #pragma unroll
        for (int d = 0; d < 64; d++) {
            float4 aq = *(const float4*)&Qs[d * QSTR + ty * 4];
            float b0 = Ks[d * KSTR + tx * 2];
            float b1 = Ks[d * KSTR + tx * 2 + 1];
            sacc[0][0] += aq.x * b0; sacc[0][1] += aq.x * b1;
            sacc[1][0] += aq.y * b0; sacc[1][1] += aq.y * b1;
            sacc[2][0] += aq.z * b0; sacc[2][1] += aq.z * b1;
            sacc[3][0] += aq.w * b0; sacc[3][1] += aq.w * b1;
        }
        #pragma unroll
        for (int i = 0; i < 4; i++) {
            Ps[(ty * 4 + i) * KSTR + tx * 2]     = sacc[i][0];
            Ps[(ty * 4 + i) * KSTR + tx * 2 + 1] = sacc[i][1];
        }
        __syncthreads();

        // online softmax: 4 threads per row, 8 cols each
        {
            int r = tid >> 2, part = tid & 3;
            float rm = -INFINITY;
            #pragma unroll
            for (int i = 0; i < 8; i++)
                rm = fmaxf(rm, Ps[r * KSTR + part * 8 + i]);
            rm = fmaxf(rm, __shfl_xor_sync(0xFFFFFFFFu, rm, 1));
            rm = fmaxf(rm, __shfl_xor_sync(0xFFFFFFFFu, rm, 2));
            float mo = mrow[r];
            float nm = fmaxf(mo, rm);
            float psum = 0.f;
            #pragma unroll
            for (int i = 0; i < 8; i++) {
                float p = __expf(Ps[r * KSTR + part * 8 + i] - nm);
                Ps[r * KSTR + part * 8 + i] = p;
                psum += p;
            }
            psum += __shfl_xor_sync(0xFFFFFFFFu, psum, 1);
            psum += __shfl_xor_sync(0xFFFFFFFFu, psum, 2);
            if (part == 0) {
                float a = __expf(mo - nm);
                arow[r] = a;
                lrow[r] = lrow[r] * a + psum;
                mrow[r] = nm;
            }
        }
        __syncthreads();

        // O = O*alpha + P V  (thread: 4q x 4d at d-slice tx*4)
        float al[4];
        #pragma unroll
        for (int i = 0; i < 4; i++) al[i] = arow[ty * 4 + i];
        #pragma unroll
        for (int i = 0; i < 4; i++)
            #pragma unroll
            for (int j = 0; j < 4; j++) oacc[i][j] *= al[i];
        #pragma unroll
        for (int k = 0; k < KSUB; k++) {
            float4 v4 = *(const float4*)&Vs[k * QSTR + tx * 4];
            float p0 = Ps[(ty * 4 + 0) * KSTR + k];
            float p1 = Ps[(ty * 4 + 1) * KSTR + k];
            float p2 = Ps[(ty * 4 + 2) * KSTR + k];
            float p3 = Ps[(ty * 4 + 3) * KSTR + k];
            oacc[0][0] += p0 * v4.x; oacc[0][1] += p0 * v4.y;
            oacc[0][2] += p0 * v4.z; oacc[0][3] += p0 * v4.w;
            oacc[1][0] += p1 * v4.x; oacc[1][1] += p1 * v4.y;
            oacc[1][2] += p1 * v4.z; oacc[1][3] += p1 * v4.w;
            oacc[2][0] += p2 * v4.x; oacc[2][1] += p2 * v4.y;
            oacc[2][2] += p2 * v4.z; oacc[2][3] += p2 * v4.w;
            oacc[3][0] += p3 * v4.x; oacc[3][1] += p3 * v4.y;
            oacc[3][2] += p3 * v4.z; oacc[3][3] += p3 * v4.w;
        }
    }

    if (single) {
        #pragma unroll
        for (int i = 0; i < 4; i++) {
            float inv = 1.0f / lrow[ty * 4 + i];
            float4 o = make_float4(oacc[i][0] * inv, oacc[i][1] * inv,
                                   oacc[i][2] * inv, oacc[i][3] * inv);
            *(float4*)&g_ao[(size_t)(qb * 64 + ty * 4 + i) * DD + h * DH + tx * 4] = o;
        }
    } else {
        int pidx = (qb * HEADS + h) * NCHUNK + c;
        #pragma unroll
        for (int i = 0; i < 4; i++) {
            float4 o = make_float4(oacc[i][0], oacc[i][1], oacc[i][2], oacc[i][3]);
            *(float4*)&g_pO[((size_t)pidx * 64 + ty * 4 + i) * 64 + tx * 4] = o;
        }
        if (tid < 64) {
            g_pm[pidx * 64 + tid] = mrow[tid];
            g_pl[pidx * 64 + tid] = lrow[tid];
        }
    }
}

// merge 8 split-KV partials per (q,h) row (flash-decoding combine)
__global__ __launch_bounds__(64)
void attn_combine(const int* __restrict__ um_p) {
    int q = blockIdx.x, h = blockIdx.y;
    int qb = q >> 6, qq = q & 63;
    int um = *um_p;
    if (um && qb < B_X) return;   // attn_flash wrote these directly
    int d = threadIdx.x;
    int pbase = (qb * HEADS + h) * NCHUNK;
    float mv[NCHUNK], lv[NCHUNK];
    float M = -INFINITY;
    #pragma unroll
    for (int c = 0; c < NCHUNK; c++) {
        mv[c] = g_pm[(pbase + c) * 64 + qq];
        lv[c] = g_pl[(pbase + c) * 64 + qq];
        M = fmaxf(M, mv[c]);
    }
    float L = 0.f, o = 0.f;
    #pragma unroll
    for (int c = 0; c < NCHUNK; c++) {
        float e = __expf(mv[c] - M);
        L += lv[c] * e;
        o += g_pO[((size_t)(pbase + c) * 64 + qq) * 64 + d] * e;
    }
    g_ao[(size_t)q * DD + h * DH + d] = o / L;
}

// ---------------- launch ----------------
extern "C" void kernel_launch(void* const* d_in, const int* in_sizes, int n_in,
                              void* d_out, int out_size) {
    const float* x    = (const float*)d_in[0];
    const float* lat  = (const float*)d_in[1];
    const float* g1   = (const float*)d_in[2];
    const float* b1   = (const float*)d_in[3];
    const float* g2   = (const float*)d_in[4];
    const float* b2   = (const float*)d_in[5];
    const float* Wq   = (const float*)d_in[6];
    const float* Wkv  = (const float*)d_in[7];
    const float* Wout = (const float*)d_in[8];
    const int*   um   = (const int*)d_in[9];
    float* out = (float*)d_out;

    // 1. LayerNorms
    ln_kernel<<<ROWS_X + ROWS_LAT, 256>>>(x, lat, g1, b1, g2, b2);

    // 2. Q = lnlat @ Wq           (576 x 1024 x 1024)
    sgemm<GEMM_Q><<<dim3(DD / BN, (ROWS_LAT + BM - 1) / BM), 256>>>(Wq, nullptr, ROWS_LAT, DD, DD);

    // 3. KV = kvin @ Wkv          (2560 x 2048 x 1024)
    sgemm<GEMM_KV><<<dim3(2 * DD / BN, ROWS_KV / BM), 256>>>(Wkv, nullptr, ROWS_KV, 2 * DD, DD);

    // 4. flash attention (query-tiled, split-KV, static smem) + combine
    attn_flash<<<NPART, 256>>>(um);
    attn_combine<<<dim3(ROWS_LAT, HEADS), 64>>>(um);

    // 5. out = ao @ Wout          (576 x 1024 x 1024), straight into d_out
    sgemm<GEMM_OUT><<<dim3(DD / BN, (ROWS_LAT + BM - 1) / BM), 256>>>(Wout, out, ROWS_LAT, DD, DD);
}

// round 7
// speedup vs baseline: 2.8487x; 1.8588x over previous
#include <cuda_runtime.h>
#include <cuda_bf16.h>
#include <math.h>
#include <stdint.h>

#define DD 1024
#define HEADS 16
#define DH 64
#define B_LAT 9
#define B_X 8
#define N_KV 256
#define N_Q 64
#define KV_PER_B (N_KV + N_Q)       /* 320  */
#define ROWS_X (B_X * N_KV)         /* 2048 */
#define ROWS_LAT (B_LAT * N_Q)      /* 576  */
#define ROWS_KV (B_X * KV_PER_B)    /* 2560 */
#define EPS 1e-5f
#define NCHUNK 8
#define NPART (B_LAT * HEADS * NCHUNK)   /* 1152 */
#define K3 3072                     /* split-bf16 extended K = 3*1024 */

// ---------------- scratch (static device globals; no allocation) ----------------
__device__ float g_kvin[ROWS_KV * DD];
__device__ float g_lnlat[ROWS_LAT * DD];
__device__ float g_q[ROWS_LAT * DD];
__device__ float g_kv[ROWS_KV * 2 * DD];
__device__ float g_ao[ROWS_LAT * DD];
__device__ float g_pO[(size_t)NPART * 64 * 64];
__device__ float g_pm[NPART * 64];
__device__ float g_pl[NPART * 64];
// split-bf16 operands: A3 = [Ah | Ah | Al] rows [M,3072]; W3 = [Wh | Wl | Wh] rows [N,3072]
__device__ __nv_bfloat16 g_a3kv[(size_t)ROWS_KV * K3];
__device__ __nv_bfloat16 g_a3small[(size_t)ROWS_LAT * K3];
__device__ __nv_bfloat16 g_w3q[(size_t)DD * K3];
__device__ __nv_bfloat16 g_w3kv[(size_t)(2 * DD) * K3];
__device__ __nv_bfloat16 g_w3out[(size_t)DD * K3];

// ---------------- PTX helpers (base ISA only: sm_80-compatible) ----------------
__device__ __forceinline__ uint32_t smem_u32(const void* p) {
    uint32_t a;
    asm("{ .reg .u64 t; cvta.to.shared.u64 t, %1; cvt.u32.u64 %0, t; }" : "=r"(a) : "l"(p));
    return a;
}
__device__ __forceinline__ void cp_async16(uint32_t s, const void* g, int sz) {
    asm volatile("cp.async.cg.shared.global [%0], [%1], 16, %2;"
                 :: "r"(s), "l"(g), "r"(sz) : "memory");
}
#define CP_COMMIT() asm volatile("cp.async.commit_group;" ::: "memory")
#define CP_WAIT0()  asm volatile("cp.async.wait_group 0;" ::: "memory")

__device__ __forceinline__ void ldm_x4(uint32_t* r, uint32_t a) {
    asm volatile("ldmatrix.sync.aligned.m8n8.x4.shared.b16 {%0,%1,%2,%3}, [%4];"
                 : "=r"(r[0]), "=r"(r[1]), "=r"(r[2]), "=r"(r[3]) : "r"(a));
}
__device__ __forceinline__ void mma_bf16(float* d, const uint32_t* a, uint32_t b0, uint32_t b1) {
    asm volatile("mma.sync.aligned.m16n8k16.row.col.f32.bf16.bf16.f32 "
                 "{%0,%1,%2,%3}, {%4,%5,%6,%7}, {%8,%9}, {%0,%1,%2,%3};"
                 : "+f"(d[0]), "+f"(d[1]), "+f"(d[2]), "+f"(d[3])
                 : "r"(a[0]), "r"(a[1]), "r"(a[2]), "r"(a[3]), "r"(b0), "r"(b1));
}

// ---------------- LayerNorm: one block per row, 256 threads ----------------
__global__ void ln_kernel(const float* __restrict__ x, const float* __restrict__ lat,
                          const float* __restrict__ g1, const float* __restrict__ b1,
                          const float* __restrict__ g2, const float* __restrict__ b2) {
    int row = blockIdx.x;
    const float *src, *g, *b;
    float *dst0, *dst1 = nullptr;
    if (row < ROWS_X) {
        int bb = row / N_KV, n = row % N_KV;
        src = x + (size_t)row * DD; g = g1; b = b1;
        dst0 = g_kvin + (size_t)(bb * KV_PER_B + n) * DD;
    } else {
        int lr = row - ROWS_X;
        int bb = lr / N_Q, n = lr % N_Q;
        src = lat + (size_t)lr * DD; g = g2; b = b2;
        dst0 = g_lnlat + (size_t)lr * DD;
        if (bb < B_X) dst1 = g_kvin + (size_t)(bb * KV_PER_B + N_KV + n) * DD;
    }
    int tid = threadIdx.x;
    float4 v = ((const float4*)src)[tid];
    float s  = v.x + v.y + v.z + v.w;
    float ss = v.x*v.x + v.y*v.y + v.z*v.z + v.w*v.w;
    #pragma unroll
    for (int o = 16; o; o >>= 1) {
        s  += __shfl_xor_sync(0xFFFFFFFFu, s,  o);
        ss += __shfl_xor_sync(0xFFFFFFFFu, ss, o);
    }
    __shared__ float sb[8], ssb[8];
    int wid = tid >> 5, lane = tid & 31;
    if (lane == 0) { sb[wid] = s; ssb[wid] = ss; }
    __syncthreads();
    float ts = 0.f, tss = 0.f;
    #pragma unroll
    for (int i = 0; i < 8; i++) { ts += sb[i]; tss += ssb[i]; }
    float mean = ts * (1.0f / DD);
    float var  = tss * (1.0f / DD) - mean * mean;
    float inv  = rsqrtf(var + EPS);
    float4 gg = ((const float4*)g)[tid];
    float4 bb4 = ((const float4*)b)[tid];
    float4 o;
    o.x = (v.x - mean) * inv * gg.x + bb4.x;
    o.y = (v.y - mean) * inv * gg.y + bb4.y;
    o.z = (v.z - mean) * inv * gg.z + bb4.z;
    o.w = (v.w - mean) * inv * gg.w + bb4.w;
    ((float4*)dst0)[tid] = o;
    if (dst1) ((float4*)dst1)[tid] = o;
}

// ---------------- split-bf16 conversions ----------------
enum ConvAOp { CA_KV = 0, CA_LAT = 1, CA_AO = 2 };
template <int OP>
__global__ void convA3() {
    const float* src = (OP == CA_KV) ? g_kvin : (OP == CA_LAT) ? g_lnlat : g_ao;
    __nv_bfloat16* dst = (OP == CA_KV) ? g_a3kv : g_a3small;
    const int rows = (OP == CA_KV) ? ROWS_KV : ROWS_LAT;
    int idx = blockIdx.x * 256 + threadIdx.x;
    if (idx >= rows * DD) return;
    int m = idx >> 10, k = idx & 1023;
    float a = src[idx];
    __nv_bfloat16 h = __float2bfloat16(a);
    __nv_bfloat16 l = __float2bfloat16(a - __bfloat162float(h));
    size_t o = (size_t)m * K3 + k;
    dst[o] = h; dst[o + 1024] = h; dst[o + 2048] = l;
}

enum ConvWOp { CW_Q = 0, CW_KV = 1, CW_OUT = 2 };
template <int OP>
__global__ void convW3(const float* __restrict__ W) {   // W [1024, N] -> dst [N, 3072]
    constexpr int N = (OP == CW_KV) ? 2 * DD : DD;
    __nv_bfloat16* dst = (OP == CW_Q) ? g_w3q : (OP == CW_KV) ? g_w3kv : g_w3out;
    __shared__ float t[32][33];
    int n0 = blockIdx.x * 32, k0 = blockIdx.y * 32;
    int tx = threadIdx.x, ty = threadIdx.y;
    #pragma unroll
    for (int j = 0; j < 4; j++)
        t[ty + j * 8][tx] = W[(size_t)(k0 + ty + j * 8) * N + n0 + tx];
    __syncthreads();
    #pragma unroll
    for (int j = 0; j < 4; j++) {
        int n = n0 + ty + j * 8, k = k0 + tx;
        float a = t[tx][ty + j * 8];
        __nv_bfloat16 h = __float2bfloat16(a);
        __nv_bfloat16 l = __float2bfloat16(a - __bfloat162float(h));
        size_t o = (size_t)n * K3 + k;
        dst[o] = h; dst[o + 1024] = l; dst[o + 2048] = h;
    }
}

// ---------------- mma.sync bf16 GEMM: C[M,N] = A3[M,3072] * W3[N,3072]^T ----------------
// 128x128x64 CTA tile, 8 warps (2x4), warp = 64x32 via 4x4 m16n8k16 tiles,
// cp.async double-buffered smem, padded stride for conflict-free ldmatrix.
#define GBK 64
#define KST 72                               /* padded row stride, bf16 elems */
#define ABUF (128 * KST * 2)                 /* 18432 B per operand tile */
#define STAGE (2 * ABUF)                     /* 36864 B per stage */
#define GEMM_SMEM (2 * STAGE)                /* 73728 B */
#define NCH (K3 / GBK)                       /* 48 */

enum GemmOp { G_Q = 0, G_KV = 1, G_OUT = 2 };

template <int OP>
__global__ __launch_bounds__(256)
void gemm_bf3(float* __restrict__ Cext) {
    constexpr int M = (OP == G_KV) ? ROWS_KV : ROWS_LAT;
    constexpr int N = (OP == G_KV) ? 2 * DD : DD;
    const __nv_bfloat16* A3 = (OP == G_KV) ? g_a3kv : g_a3small;
    const __nv_bfloat16* B3 = (OP == G_Q) ? g_w3q : (OP == G_KV) ? g_w3kv : g_w3out;
    float* C = (OP == G_Q) ? g_q : (OP == G_KV) ? g_kv : Cext;

    extern __shared__ __align__(16) unsigned char dynsm[];
    int tid = threadIdx.x, wid = tid >> 5, lane = tid & 31;
    int br = blockIdx.y * 128, bc = blockIdx.x * 128;
    int wm = (wid >> 2) * 64;      // warp row offset within tile
    int wn = (wid & 3) * 32;       // warp col offset within tile

    // issue one 128x64 A chunk + 128x64 B chunk into stage buf via cp.async
    auto issue = [&](int kb, int buf) {
        unsigned char* sb = dynsm + buf * STAGE;
        const __nv_bfloat16* Ab = A3 + (size_t)0 + kb * GBK;
        const __nv_bfloat16* Bb = B3 + (size_t)bc * K3 + kb * GBK;
        #pragma unroll
        for (int j = 0; j < 4; j++) {
            int idx = tid + j * 256;           // 0..1023
            int r = idx >> 3, c8 = idx & 7;
            // A row (clamped; zero-fill OOB via src-size=0)
            int gr = br + r; int sz = (gr < M) ? 16 : 0;
            if (gr >= M) gr = M - 1;
            cp_async16(smem_u32(sb + (r * KST + c8 * 8) * 2),
                       Ab + (size_t)gr * K3 + c8 * 8, sz);
            // B row (N is a multiple of 128 -> always in bounds)
            cp_async16(smem_u32(sb + ABUF + (r * KST + c8 * 8) * 2),
                       Bb + (size_t)r * K3 + c8 * 8, 16);
        }
        CP_COMMIT();
    };

    float acc[4][4][4] = {};

    issue(0, 0);
    CP_WAIT0();
    __syncthreads();

    for (int kb = 0; kb < NCH; kb++) {
        int cur = kb & 1;
        if (kb + 1 < NCH) issue(kb + 1, cur ^ 1);

        const unsigned char* sA = dynsm + cur * STAGE;
        const unsigned char* sB = sA + ABUF;
        #pragma unroll
        for (int ks = 0; ks < 4; ks++) {
            int k0 = ks * 16;
            uint32_t a[4][4];
            #pragma unroll
            for (int mt = 0; mt < 4; mt++) {
                int arow = wm + mt * 16 + (lane & 15);
                int acol = k0 + (lane >> 4) * 8;
                ldm_x4(a[mt], smem_u32(sA + (arow * KST + acol) * 2));
            }
            uint32_t b[2][4];
            #pragma unroll
            for (int np = 0; np < 2; np++) {
                int nrow = wn + np * 16 + (lane & 7) + ((lane >> 4) << 3);
                int kcol = k0 + ((lane >> 3) & 1) * 8;
                ldm_x4(b[np], smem_u32(sB + (nrow * KST + kcol) * 2));
            }
            #pragma unroll
            for (int mt = 0; mt < 4; mt++)
                #pragma unroll
                for (int nt = 0; nt < 4; nt++)
                    mma_bf16(acc[mt][nt], a[mt], b[nt >> 1][(nt & 1) * 2],
                             b[nt >> 1][(nt & 1) * 2 + 1]);
        }
        if (kb + 1 < NCH) CP_WAIT0();
        __syncthreads();
    }

    // epilogue: fragment rows -> global
    #pragma unroll
    for (int mt = 0; mt < 4; mt++) {
        int r0 = br + wm + mt * 16 + (lane >> 2);
        #pragma unroll
        for (int nt = 0; nt < 4; nt++) {
            int c = bc + wn + nt * 8 + (lane & 3) * 2;
            if (r0 < M)
                *(float2*)&C[(size_t)r0 * N + c] = make_float2(acc[mt][nt][0], acc[mt][nt][1]);
            if (r0 + 8 < M)
                *(float2*)&C[(size_t)(r0 + 8) * N + c] = make_float2(acc[mt][nt][2], acc[mt][nt][3]);
        }
    }
}

// ---------------- flash attention (unchanged from R5) ----------------
#define QSTR 68
#define KSTR 36
#define KSUB 32

__global__ __launch_bounds__(256)
void attn_flash(const int* __restrict__ um_p) {
    int b  = blockIdx.x;
    int qb = b >> 7;
    int h  = (b >> 3) & 15;
    int c  = b & 7;
    int um = *um_p;
    bool single = (um != 0) && (qb < B_X);
    if (single && c != qb) return;

    __shared__ float Qs[64 * QSTR];
    __shared__ float Ks[64 * KSTR];
    __shared__ float Vs[KSUB * QSTR];
    __shared__ float Ps[64 * KSTR];
    __shared__ float mrow[64], lrow[64], arow[64];

    int tid = threadIdx.x;
    int ty = tid >> 4, tx = tid & 15;

    #pragma unroll
    for (int it = 0; it < 4; it++) {
        int row = ty + it * 16;
        int col = tx * 4;
        float4 v = *(const float4*)&g_q[(size_t)(qb * 64 + row) * DD + h * DH + col];
        Qs[(col + 0) * QSTR + row] = v.x * 0.125f;
        Qs[(col + 1) * QSTR + row] = v.y * 0.125f;
        Qs[(col + 2) * QSTR + row] = v.z * 0.125f;
        Qs[(col + 3) * QSTR + row] = v.w * 0.125f;
    }
    if (tid < 64) { mrow[tid] = -INFINITY; lrow[tid] = 0.f; }

    float oacc[4][4] = {};
    int ks0 = c * KV_PER_B;

    for (int sub = 0; sub < 10; sub++) {
        int kb = ks0 + sub * KSUB;
        __syncthreads();
        {
            int r = tid >> 4;
            int c4 = (tid & 15) * 4;
            const float* base0 = g_kv + (size_t)(kb + r) * (2 * DD) + h * DH + c4;
            float4 kk = *(const float4*)base0;
            Ks[(c4 + 0) * KSTR + r] = kk.x;
            Ks[(c4 + 1) * KSTR + r] = kk.y;
            Ks[(c4 + 2) * KSTR + r] = kk.z;
            Ks[(c4 + 3) * KSTR + r] = kk.w;
            *(float4*)&Vs[r * QSTR + c4] = *(const float4*)(base0 + DD);
            int r2 = r + 16;
            const float* base1 = g_kv + (size_t)(kb + r2) * (2 * DD) + h * DH + c4;
            float4 k2 = *(const float4*)base1;
            Ks[(c4 + 0) * KSTR + r2] = k2.x;
            Ks[(c4 + 1) * KSTR + r2] = k2.y;
            Ks[(c4 + 2) * KSTR + r2] = k2.z;
            Ks[(c4 + 3) * KSTR + r2] = k2.w;
            *(float4*)&Vs[r2 * QSTR + c4] = *(const float4*)(base1 + DD);
        }
        __syncthreads();

        float sacc[4][2] = {};
        #pragma unroll
        for (int d = 0; d < 64; d++) {
            float4 aq = *(const float4*)&Qs[d * QSTR + ty * 4];
            float b0 = Ks[d * KSTR + tx * 2];
            float b1 = Ks[d * KSTR + tx * 2 + 1];
            sacc[0][0] += aq.x * b0; sacc[0][1] += aq.x * b1;
            sacc[1][0] += aq.y * b0; sacc[1][1] += aq.y * b1;
            sacc[2][0] += aq.z * b0; sacc[2][1] += aq.z * b1;
            sacc[3][0] += aq.w * b0; sacc[3][1] += aq.w * b1;
        }
        #pragma unroll
        for (int i = 0; i < 4; i++) {
            Ps[(ty * 4 + i) * KSTR + tx * 2]     = sacc[i][0];
            Ps[(ty * 4 + i) * KSTR + tx * 2 + 1] = sacc[i][1];
        }
        __syncthreads();

        {
            int r = tid >> 2, part = tid & 3;
            float rm = -INFINITY;
            #pragma unroll
            for (int i = 0; i < 8; i++)
                rm = fmaxf(rm, Ps[r * KSTR + part * 8 + i]);
            rm = fmaxf(rm, __shfl_xor_sync(0xFFFFFFFFu, rm, 1));
            rm = fmaxf(rm, __shfl_xor_sync(0xFFFFFFFFu, rm, 2));
            float mo = mrow[r];
            float nm = fmaxf(mo, rm);
            float psum = 0.f;
            #pragma unroll
            for (int i = 0; i < 8; i++) {
                float p = __expf(Ps[r * KSTR + part * 8 + i] - nm);
                Ps[r * KSTR + part * 8 + i] = p;
                psum += p;
            }
            psum += __shfl_xor_sync(0xFFFFFFFFu, psum, 1);
            psum += __shfl_xor_sync(0xFFFFFFFFu, psum, 2);
            if (part == 0) {
                float a = __expf(mo - nm);
                arow[r] = a;
                lrow[r] = lrow[r] * a + psum;
                mrow[r] = nm;
            }
        }
        __syncthreads();

        float al[4];
        #pragma unroll
        for (int i = 0; i < 4; i++) al[i] = arow[ty * 4 + i];
        #pragma unroll
        for (int i = 0; i < 4; i++)
            #pragma unroll
            for (int j = 0; j < 4; j++) oacc[i][j] *= al[i];
        #pragma unroll
        for (int k = 0; k < KSUB; k++) {
            float4 v4 = *(const float4*)&Vs[k * QSTR + tx * 4];
            float p0 = Ps[(ty * 4 + 0) * KSTR + k];
            float p1 = Ps[(ty * 4 + 1) * KSTR + k];
            float p2 = Ps[(ty * 4 + 2) * KSTR + k];
            float p3 = Ps[(ty * 4 + 3) * KSTR + k];
            oacc[0][0] += p0 * v4.x; oacc[0][1] += p0 * v4.y;
            oacc[0][2] += p0 * v4.z; oacc[0][3] += p0 * v4.w;
            oacc[1][0] += p1 * v4.x; oacc[1][1] += p1 * v4.y;
            oacc[1][2] += p1 * v4.z; oacc[1][3] += p1 * v4.w;
            oacc[2][0] += p2 * v4.x; oacc[2][1] += p2 * v4.y;
            oacc[2][2] += p2 * v4.z; oacc[2][3] += p2 * v4.w;
            oacc[3][0] += p3 * v4.x; oacc[3][1] += p3 * v4.y;
            oacc[3][2] += p3 * v4.z; oacc[3][3] += p3 * v4.w;
        }
    }

    if (single) {
        #pragma unroll
        for (int i = 0; i < 4; i++) {
            float inv = 1.0f / lrow[ty * 4 + i];
            float4 o = make_float4(oacc[i][0] * inv, oacc[i][1] * inv,
                                   oacc[i][2] * inv, oacc[i][3] * inv);
            *(float4*)&g_ao[(size_t)(qb * 64 + ty * 4 + i) * DD + h * DH + tx * 4] = o;
        }
    } else {
        int pidx = (qb * HEADS + h) * NCHUNK + c;
        #pragma unroll
        for (int i = 0; i < 4; i++) {
            float4 o = make_float4(oacc[i][0], oacc[i][1], oacc[i][2], oacc[i][3]);
            *(float4*)&g_pO[((size_t)pidx * 64 + ty * 4 + i) * 64 + tx * 4] = o;
        }
        if (tid < 64) {
            g_pm[pidx * 64 + tid] = mrow[tid];
            g_pl[pidx * 64 + tid] = lrow[tid];
        }
    }
}

__global__ __launch_bounds__(64)
void attn_combine(const int* __restrict__ um_p) {
    int q = blockIdx.x, h = blockIdx.y;
    int qb = q >> 6, qq = q & 63;
    int um = *um_p;
    if (um && qb < B_X) return;
    int d = threadIdx.x;
    int pbase = (qb * HEADS + h) * NCHUNK;
    float mv[NCHUNK], lv[NCHUNK];
    float M = -INFINITY;
    #pragma unroll
    for (int c = 0; c < NCHUNK; c++) {
        mv[c] = g_pm[(pbase + c) * 64 + qq];
        lv[c] = g_pl[(pbase + c) * 64 + qq];
        M = fmaxf(M, mv[c]);
    }
    float L = 0.f, o = 0.f;
    #pragma unroll
    for (int c = 0; c < NCHUNK; c++) {
        float e = __expf(mv[c] - M);
        L += lv[c] * e;
        o += g_pO[((size_t)(pbase + c) * 64 + qq) * 64 + d] * e;
    }
    g_ao[(size_t)q * DD + h * DH + d] = o / L;
}

// ---------------- launch ----------------
extern "C" void kernel_launch(void* const* d_in, const int* in_sizes, int n_in,
                              void* d_out, int out_size) {
    const float* x    = (const float*)d_in[0];
    const float* lat  = (const float*)d_in[1];
    const float* g1   = (const float*)d_in[2];
    const float* b1   = (const float*)d_in[3];
    const float* g2   = (const float*)d_in[4];
    const float* b2   = (const float*)d_in[5];
    const float* Wq   = (const float*)d_in[6];
    const float* Wkv  = (const float*)d_in[7];
    const float* Wout = (const float*)d_in[8];
    const int*   um   = (const int*)d_in[9];
    float* out = (float*)d_out;

    cudaFuncSetAttribute(gemm_bf3<G_Q>,   cudaFuncAttributeMaxDynamicSharedMemorySize, GEMM_SMEM);
    cudaFuncSetAttribute(gemm_bf3<G_KV>,  cudaFuncAttributeMaxDynamicSharedMemorySize, GEMM_SMEM);
    cudaFuncSetAttribute(gemm_bf3<G_OUT>, cudaFuncAttributeMaxDynamicSharedMemorySize, GEMM_SMEM);

    // 1. LayerNorms
    ln_kernel<<<ROWS_X + ROWS_LAT, 256>>>(x, lat, g1, b1, g2, b2);

    // 2. split-bf16 conversions (A side + transposed W side)
    convA3<CA_KV><<<(ROWS_KV * DD + 255) / 256, 256>>>();
    convA3<CA_LAT><<<(ROWS_LAT * DD + 255) / 256, 256>>>();
    convW3<CW_Q><<<dim3(DD / 32, DD / 32), dim3(32, 8)>>>(Wq);
    convW3<CW_KV><<<dim3(2 * DD / 32, DD / 32), dim3(32, 8)>>>(Wkv);
    convW3<CW_OUT><<<dim3(DD / 32, DD / 32), dim3(32, 8)>>>(Wout);

    // 3. Q and KV projections on tensor cores (mma.sync)
    gemm_bf3<G_Q><<<dim3(DD / 128, (ROWS_LAT + 127) / 128), 256, GEMM_SMEM>>>(nullptr);
    gemm_bf3<G_KV><<<dim3(2 * DD / 128, ROWS_KV / 128), 256, GEMM_SMEM>>>(nullptr);

    // 4. flash attention + combine
    attn_flash<<<NPART, 256>>>(um);
    attn_combine<<<dim3(ROWS_LAT, HEADS), 64>>>(um);

    // 5. output projection
    convA3<CA_AO><<<(ROWS_LAT * DD + 255) / 256, 256>>>();
    gemm_bf3<G_OUT><<<dim3(DD / 128, (ROWS_LAT + 127) / 128), 256, GEMM_SMEM>>>(out);
}

// round 8
// speedup vs baseline: 3.1707x; 1.1131x over previous
#include <cuda_runtime.h>
#include <cuda_bf16.h>
#include <math.h>
#include <stdint.h>

#define DD 1024
#define HEADS 16
#define DH 64
#define B_LAT 9
#define B_X 8
#define N_KV 256
#define N_Q 64
#define KV_PER_B (N_KV + N_Q)       /* 320  */
#define ROWS_X (B_X * N_KV)         /* 2048 */
#define ROWS_LAT (B_LAT * N_Q)      /* 576  */
#define ROWS_KV (B_X * KV_PER_B)    /* 2560 */
#define EPS 1e-5f
#define NCHUNK 8
#define NPART (B_LAT * HEADS * NCHUNK)   /* 1152 */
#define K3 3072                     /* split-bf16 extended K = 3*1024 */

// ---------------- scratch (static device globals; no allocation) ----------------
__device__ float g_q[ROWS_LAT * DD];
__device__ float g_kv[ROWS_KV * 2 * DD];
__device__ float g_pO[(size_t)NPART * 64 * 64];
__device__ float g_pm[NPART * 64];
__device__ float g_pl[NPART * 64];
// split-bf16 operands: A3 = [Ah | Ah | Al] rows [M,3072]; W3 = [Wh | Wl | Wh] rows [N,3072]
__device__ __nv_bfloat16 g_a3kv[(size_t)ROWS_KV * K3];
__device__ __nv_bfloat16 g_a3small[(size_t)ROWS_LAT * K3];   // lnlat splits, later ao splits
__device__ __nv_bfloat16 g_w3q[(size_t)DD * K3];
__device__ __nv_bfloat16 g_w3kv[(size_t)(2 * DD) * K3];
__device__ __nv_bfloat16 g_w3out[(size_t)DD * K3];

// ---------------- PTX helpers (base ISA only: sm_80-compatible) ----------------
__device__ __forceinline__ uint32_t smem_u32(const void* p) {
    uint32_t a;
    asm("{ .reg .u64 t; cvta.to.shared.u64 t, %1; cvt.u32.u64 %0, t; }" : "=r"(a) : "l"(p));
    return a;
}
__device__ __forceinline__ void cp_async16(uint32_t s, const void* g, int sz) {
    asm volatile("cp.async.cg.shared.global [%0], [%1], 16, %2;"
                 :: "r"(s), "l"(g), "r"(sz) : "memory");
}
#define CP_COMMIT() asm volatile("cp.async.commit_group;" ::: "memory")
#define CP_WAIT0()  asm volatile("cp.async.wait_group 0;" ::: "memory")

__device__ __forceinline__ void ldm_x4(uint32_t* r, uint32_t a) {
    asm volatile("ldmatrix.sync.aligned.m8n8.x4.shared.b16 {%0,%1,%2,%3}, [%4];"
                 : "=r"(r[0]), "=r"(r[1]), "=r"(r[2]), "=r"(r[3]) : "r"(a));
}
__device__ __forceinline__ void mma_bf16(float* d, const uint32_t* a, uint32_t b0, uint32_t b1) {
    asm volatile("mma.sync.aligned.m16n8k16.row.col.f32.bf16.bf16.f32 "
                 "{%0,%1,%2,%3}, {%4,%5,%6,%7}, {%8,%9}, {%0,%1,%2,%3};"
                 : "+f"(d[0]), "+f"(d[1]), "+f"(d[2]), "+f"(d[3])
                 : "r"(a[0]), "r"(a[1]), "r"(a[2]), "r"(a[3]), "r"(b0), "r"(b1));
}

// store 4 fp32 values as split-bf16 triple at dst[0], dst[1024], dst[2048]
// layout flags: A-side (h,h,l) ; W-side handled separately.
__device__ __forceinline__ void store_split4_A(__nv_bfloat16* dst, float4 v) {
    __nv_bfloat16 h0 = __float2bfloat16(v.x), h1 = __float2bfloat16(v.y);
    __nv_bfloat16 h2 = __float2bfloat16(v.z), h3 = __float2bfloat16(v.w);
    __nv_bfloat16 l0 = __float2bfloat16(v.x - __bfloat162float(h0));
    __nv_bfloat16 l1 = __float2bfloat16(v.y - __bfloat162float(h1));
    __nv_bfloat16 l2 = __float2bfloat16(v.z - __bfloat162float(h2));
    __nv_bfloat16 l3 = __float2bfloat16(v.w - __bfloat162float(h3));
    __nv_bfloat162 H0 = {h0, h1}, H1 = {h2, h3}, L0 = {l0, l1}, L1 = {l2, l3};
    *(__nv_bfloat162*)&dst[0]        = H0; *(__nv_bfloat162*)&dst[2]        = H1;
    *(__nv_bfloat162*)&dst[1024]     = H0; *(__nv_bfloat162*)&dst[1026]     = H1;
    *(__nv_bfloat162*)&dst[2048]     = L0; *(__nv_bfloat162*)&dst[2050]     = L1;
}

// ---------------- LayerNorm: one block per row, 256 threads; emits split-bf16 ----------------
__global__ void ln_kernel(const float* __restrict__ x, const float* __restrict__ lat,
                          const float* __restrict__ g1, const float* __restrict__ b1,
                          const float* __restrict__ g2, const float* __restrict__ b2) {
    int row = blockIdx.x;
    const float *src, *g, *b;
    __nv_bfloat16 *dst0, *dst1 = nullptr;
    if (row < ROWS_X) {
        int bb = row / N_KV, n = row % N_KV;
        src = x + (size_t)row * DD; g = g1; b = b1;
        dst0 = g_a3kv + (size_t)(bb * KV_PER_B + n) * K3;
    } else {
        int lr = row - ROWS_X;
        int bb = lr / N_Q, n = lr % N_Q;
        src = lat + (size_t)lr * DD; g = g2; b = b2;
        dst0 = g_a3small + (size_t)lr * K3;
        if (bb < B_X) dst1 = g_a3kv + (size_t)(bb * KV_PER_B + N_KV + n) * K3;
    }
    int tid = threadIdx.x;
    float4 v = ((const float4*)src)[tid];
    float s  = v.x + v.y + v.z + v.w;
    float ss = v.x*v.x + v.y*v.y + v.z*v.z + v.w*v.w;
    #pragma unroll
    for (int o = 16; o; o >>= 1) {
        s  += __shfl_xor_sync(0xFFFFFFFFu, s,  o);
        ss += __shfl_xor_sync(0xFFFFFFFFu, ss, o);
    }
    __shared__ float sb[8], ssb[8];
    int wid = tid >> 5, lane = tid & 31;
    if (lane == 0) { sb[wid] = s; ssb[wid] = ss; }
    __syncthreads();
    float ts = 0.f, tss = 0.f;
    #pragma unroll
    for (int i = 0; i < 8; i++) { ts += sb[i]; tss += ssb[i]; }
    float mean = ts * (1.0f / DD);
    float var  = tss * (1.0f / DD) - mean * mean;
    float inv  = rsqrtf(var + EPS);
    float4 gg = ((const float4*)g)[tid];
    float4 bb4 = ((const float4*)b)[tid];
    float4 o;
    o.x = (v.x - mean) * inv * gg.x + bb4.x;
    o.y = (v.y - mean) * inv * gg.y + bb4.y;
    o.z = (v.z - mean) * inv * gg.z + bb4.z;
    o.w = (v.w - mean) * inv * gg.w + bb4.w;
    store_split4_A(dst0 + tid * 4, o);
    if (dst1) store_split4_A(dst1 + tid * 4, o);
}

// ---------------- W conversions: W [1024, N] -> [N, 3072] as [Wh | Wl | Wh] ----------------
enum ConvWOp { CW_Q = 0, CW_KV = 1, CW_OUT = 2 };
template <int OP>
__global__ void convW3(const float* __restrict__ W) {
    constexpr int N = (OP == CW_KV) ? 2 * DD : DD;
    __nv_bfloat16* dst = (OP == CW_Q) ? g_w3q : (OP == CW_KV) ? g_w3kv : g_w3out;
    __shared__ float t[32][33];
    int n0 = blockIdx.x * 32, k0 = blockIdx.y * 32;
    int tx = threadIdx.x, ty = threadIdx.y;
    #pragma unroll
    for (int j = 0; j < 4; j++)
        t[ty + j * 8][tx] = W[(size_t)(k0 + ty + j * 8) * N + n0 + tx];
    __syncthreads();
    #pragma unroll
    for (int j = 0; j < 4; j++) {
        int n = n0 + ty + j * 8, k = k0 + tx;
        float a = t[tx][ty + j * 8];
        __nv_bfloat16 h = __float2bfloat16(a);
        __nv_bfloat16 l = __float2bfloat16(a - __bfloat162float(h));
        size_t o = (size_t)n * K3 + k;
        dst[o] = h; dst[o + 1024] = l; dst[o + 2048] = h;
    }
}

// ---------------- mma.sync bf16 GEMM: C[M,N] = A3[M,3072] * W3[N,3072]^T ----------------
#define GBK 64
#define KST 72
#define ABUF (128 * KST * 2)
#define STAGE (2 * ABUF)
#define GEMM_SMEM (2 * STAGE)                /* 73728 B */
#define NCH (K3 / GBK)                       /* 48 */

enum GemmOp { G_Q = 0, G_KV = 1, G_OUT = 2 };

template <int OP>
__global__ __launch_bounds__(256)
void gemm_bf3(float* __restrict__ Cext) {
    constexpr int M = (OP == G_KV) ? ROWS_KV : ROWS_LAT;
    constexpr int N = (OP == G_KV) ? 2 * DD : DD;
    const __nv_bfloat16* A3 = (OP == G_KV) ? g_a3kv : g_a3small;
    const __nv_bfloat16* B3 = (OP == G_Q) ? g_w3q : (OP == G_KV) ? g_w3kv : g_w3out;
    float* C = (OP == G_Q) ? g_q : (OP == G_KV) ? g_kv : Cext;

    extern __shared__ __align__(16) unsigned char dynsm[];
    int tid = threadIdx.x, wid = tid >> 5, lane = tid & 31;
    int br = blockIdx.y * 128, bc = blockIdx.x * 128;
    int wm = (wid >> 2) * 64;
    int wn = (wid & 3) * 32;

    auto issue = [&](int kb, int buf) {
        unsigned char* sb = dynsm + buf * STAGE;
        const __nv_bfloat16* Ab = A3 + kb * GBK;
        const __nv_bfloat16* Bb = B3 + (size_t)bc * K3 + kb * GBK;
        #pragma unroll
        for (int j = 0; j < 4; j++) {
            int idx = tid + j * 256;
            int r = idx >> 3, c8 = idx & 7;
            int gr = br + r; int sz = (gr < M) ? 16 : 0;
            if (gr >= M) gr = M - 1;
            cp_async16(smem_u32(sb + (r * KST + c8 * 8) * 2),
                       Ab + (size_t)gr * K3 + c8 * 8, sz);
            cp_async16(smem_u32(sb + ABUF + (r * KST + c8 * 8) * 2),
                       Bb + (size_t)r * K3 + c8 * 8, 16);
        }
        CP_COMMIT();
    };

    float acc[4][4][4] = {};

    issue(0, 0);
    CP_WAIT0();
    __syncthreads();

    for (int kb = 0; kb < NCH; kb++) {
        int cur = kb & 1;
        if (kb + 1 < NCH) issue(kb + 1, cur ^ 1);

        const unsigned char* sA = dynsm + cur * STAGE;
        const unsigned char* sB = sA + ABUF;
        #pragma unroll
        for (int ks = 0; ks < 4; ks++) {
            int k0 = ks * 16;
            uint32_t a[4][4];
            #pragma unroll
            for (int mt = 0; mt < 4; mt++) {
                int arow = wm + mt * 16 + (lane & 15);
                int acol = k0 + (lane >> 4) * 8;
                ldm_x4(a[mt], smem_u32(sA + (arow * KST + acol) * 2));
            }
            uint32_t b[2][4];
            #pragma unroll
            for (int np = 0; np < 2; np++) {
                int nrow = wn + np * 16 + (lane & 7) + ((lane >> 4) << 3);
                int kcol = k0 + ((lane >> 3) & 1) * 8;
                ldm_x4(b[np], smem_u32(sB + (nrow * KST + kcol) * 2));
            }
            #pragma unroll
            for (int mt = 0; mt < 4; mt++)
                #pragma unroll
                for (int nt = 0; nt < 4; nt++)
                    mma_bf16(acc[mt][nt], a[mt], b[nt >> 1][(nt & 1) * 2],
                             b[nt >> 1][(nt & 1) * 2 + 1]);
        }
        if (kb + 1 < NCH) CP_WAIT0();
        __syncthreads();
    }

    #pragma unroll
    for (int mt = 0; mt < 4; mt++) {
        int r0 = br + wm + mt * 16 + (lane >> 2);
        #pragma unroll
        for (int nt = 0; nt < 4; nt++) {
            int c = bc + wn + nt * 8 + (lane & 3) * 2;
            if (r0 < M)
                *(float2*)&C[(size_t)r0 * N + c] = make_float2(acc[mt][nt][0], acc[mt][nt][1]);
            if (r0 + 8 < M)
                *(float2*)&C[(size_t)(r0 + 8) * N + c] = make_float2(acc[mt][nt][2], acc[mt][nt][3]);
        }
    }
}

// ---------------- flash attention: 64-query x 64-key subtiles, split-KV ----------------
// Dynamic smem (70400 B). Output written directly as split-bf16 rows of g_a3small.
#define ASTR 68

__global__ __launch_bounds__(256)
void attn_flash(const int* __restrict__ um_p) {
    int b  = blockIdx.x;
    int qb = b >> 7;
    int h  = (b >> 3) & 15;
    int c  = b & 7;
    int um = *um_p;
    bool single = (um != 0) && (qb < B_X);
    if (single && c != qb) return;   // whole block exits before any barrier

    extern __shared__ float smf[];
    float* Qs = smf;                    // [d][q] pre-scaled
    float* Ks = smf + 64 * ASTR;        // [d][k]
    float* Vs = smf + 2 * 64 * ASTR;    // [k][d]
    float* Ps = smf + 3 * 64 * ASTR;    // [q][k]
    float* mrow = smf + 4 * 64 * ASTR;
    float* lrow = mrow + 64;
    float* arow = mrow + 128;

    int tid = threadIdx.x;
    int ty = tid >> 4, tx = tid & 15;

    #pragma unroll
    for (int it = 0; it < 4; it++) {
        int row = ty + it * 16;
        int col = tx * 4;
        float4 v = *(const float4*)&g_q[(size_t)(qb * 64 + row) * DD + h * DH + col];
        Qs[(col + 0) * ASTR + row] = v.x * 0.125f;
        Qs[(col + 1) * ASTR + row] = v.y * 0.125f;
        Qs[(col + 2) * ASTR + row] = v.z * 0.125f;
        Qs[(col + 3) * ASTR + row] = v.w * 0.125f;
    }
    if (tid < 64) { mrow[tid] = -INFINITY; lrow[tid] = 0.f; }

    float oacc[4][4] = {};
    int ks0 = c * KV_PER_B;

    for (int sub = 0; sub < 5; sub++) {
        int kb = ks0 + sub * 64;
        __syncthreads();
        // K subtile transposed + V subtile row-major (64 rows, 4 iters x 256 thr)
        #pragma unroll
        for (int it = 0; it < 4; it++) {
            int row = ty + it * 16;
            int col = tx * 4;
            const float* base = g_kv + (size_t)(kb + row) * (2 * DD) + h * DH + col;
            float4 kk = *(const float4*)base;
            Ks[(col + 0) * ASTR + row] = kk.x;
            Ks[(col + 1) * ASTR + row] = kk.y;
            Ks[(col + 2) * ASTR + row] = kk.z;
            Ks[(col + 3) * ASTR + row] = kk.w;
            *(float4*)&Vs[row * ASTR + col] = *(const float4*)(base + DD);
        }
        __syncthreads();

        // S = Q K^T  (thread: 4q x 4k)
        float sacc[4][4] = {};
        #pragma unroll
        for (int d = 0; d < 64; d++) {
            float4 aq = *(const float4*)&Qs[d * ASTR + ty * 4];
            float4 bk = *(const float4*)&Ks[d * ASTR + tx * 4];
            sacc[0][0] += aq.x * bk.x; sacc[0][1] += aq.x * bk.y;
            sacc[0][2] += aq.x * bk.z; sacc[0][3] += aq.x * bk.w;
            sacc[1][0] += aq.y * bk.x; sacc[1][1] += aq.y * bk.y;
            sacc[1][2] += aq.y * bk.z; sacc[1][3] += aq.y * bk.w;
            sacc[2][0] += aq.z * bk.x; sacc[2][1] += aq.z * bk.y;
            sacc[2][2] += aq.z * bk.z; sacc[2][3] += aq.z * bk.w;
            sacc[3][0] += aq.w * bk.x; sacc[3][1] += aq.w * bk.y;
            sacc[3][2] += aq.w * bk.z; sacc[3][3] += aq.w * bk.w;
        }
        #pragma unroll
        for (int i = 0; i < 4; i++)
            #pragma unroll
            for (int j = 0; j < 4; j++)
                Ps[(ty * 4 + i) * ASTR + tx * 4 + j] = sacc[i][j];
        __syncthreads();

        // online softmax: 4 threads per row, 16 cols each
        {
            int r = tid >> 2, part = tid & 3;
            float rm = -INFINITY;
            #pragma unroll
            for (int i = 0; i < 16; i++)
                rm = fmaxf(rm, Ps[r * ASTR + part * 16 + i]);
            rm = fmaxf(rm, __shfl_xor_sync(0xFFFFFFFFu, rm, 1));
            rm = fmaxf(rm, __shfl_xor_sync(0xFFFFFFFFu, rm, 2));
            float mo = mrow[r];
            float nm = fmaxf(mo, rm);
            float psum = 0.f;
            #pragma unroll
            for (int i = 0; i < 16; i++) {
                float p = __expf(Ps[r * ASTR + part * 16 + i] - nm);
                Ps[r * ASTR + part * 16 + i] = p;
                psum += p;
            }
            psum += __shfl_xor_sync(0xFFFFFFFFu, psum, 1);
            psum += __shfl_xor_sync(0xFFFFFFFFu, psum, 2);
            if (part == 0) {
                float a = __expf(mo - nm);
                arow[r] = a;
                lrow[r] = lrow[r] * a + psum;
                mrow[r] = nm;
            }
        }
        __syncthreads();

        // O = O*alpha + P V
        float al[4];
        #pragma unroll
        for (int i = 0; i < 4; i++) al[i] = arow[ty * 4 + i];
        #pragma unroll
        for (int i = 0; i < 4; i++)
            #pragma unroll
            for (int j = 0; j < 4; j++) oacc[i][j] *= al[i];
        #pragma unroll
        for (int k = 0; k < 64; k++) {
            float4 v4 = *(const float4*)&Vs[k * ASTR + tx * 4];
            float p0 = Ps[(ty * 4 + 0) * ASTR + k];
            float p1 = Ps[(ty * 4 + 1) * ASTR + k];
            float p2 = Ps[(ty * 4 + 2) * ASTR + k];
            float p3 = Ps[(ty * 4 + 3) * ASTR + k];
            oacc[0][0] += p0 * v4.x; oacc[0][1] += p0 * v4.y;
            oacc[0][2] += p0 * v4.z; oacc[0][3] += p0 * v4.w;
            oacc[1][0] += p1 * v4.x; oacc[1][1] += p1 * v4.y;
            oacc[1][2] += p1 * v4.z; oacc[1][3] += p1 * v4.w;
            oacc[2][0] += p2 * v4.x; oacc[2][1] += p2 * v4.y;
            oacc[2][2] += p2 * v4.z; oacc[2][3] += p2 * v4.w;
            oacc[3][0] += p3 * v4.x; oacc[3][1] += p3 * v4.y;
            oacc[3][2] += p3 * v4.z; oacc[3][3] += p3 * v4.w;
        }
    }

    if (single) {
        #pragma unroll
        for (int i = 0; i < 4; i++) {
            float inv = 1.0f / lrow[ty * 4 + i];
            float4 o = make_float4(oacc[i][0] * inv, oacc[i][1] * inv,
                                   oacc[i][2] * inv, oacc[i][3] * inv);
            // write split-bf16 row of g_a3small directly (out-GEMM operand)
            store_split4_A(g_a3small + (size_t)(qb * 64 + ty * 4 + i) * K3 + h * DH + tx * 4, o);
        }
    } else {
        int pidx = (qb * HEADS + h) * NCHUNK + c;
        #pragma unroll
        for (int i = 0; i < 4; i++) {
            float4 o = make_float4(oacc[i][0], oacc[i][1], oacc[i][2], oacc[i][3]);
            *(float4*)&g_pO[((size_t)pidx * 64 + ty * 4 + i) * 64 + tx * 4] = o;
        }
        if (tid < 64) {
            g_pm[pidx * 64 + tid] = mrow[tid];
            g_pl[pidx * 64 + tid] = lrow[tid];
        }
    }
}

// merge 8 split-KV partials; emit split-bf16 directly
__global__ __launch_bounds__(64)
void attn_combine(const int* __restrict__ um_p) {
    int q = blockIdx.x, h = blockIdx.y;
    int qb = q >> 6, qq = q & 63;
    int um = *um_p;
    if (um && qb < B_X) return;
    int d = threadIdx.x;
    int pbase = (qb * HEADS + h) * NCHUNK;
    float mv[NCHUNK], lv[NCHUNK];
    float M = -INFINITY;
    #pragma unroll
    for (int c = 0; c < NCHUNK; c++) {
        mv[c] = g_pm[(pbase + c) * 64 + qq];
        lv[c] = g_pl[(pbase + c) * 64 + qq];
        M = fmaxf(M, mv[c]);
    }
    float L = 0.f, o = 0.f;
    #pragma unroll
    for (int c = 0; c < NCHUNK; c++) {
        float e = __expf(mv[c] - M);
        L += lv[c] * e;
        o += g_pO[((size_t)(pbase + c) * 64 + qq) * 64 + d] * e;
    }
    float r = o / L;
    __nv_bfloat16 hh = __float2bfloat16(r);
    __nv_bfloat16 ll = __float2bfloat16(r - __bfloat162float(hh));
    __nv_bfloat16* dst = g_a3small + (size_t)q * K3 + h * DH + d;
    dst[0] = hh; dst[1024] = hh; dst[2048] = ll;
}

// ---------------- launch ----------------
#define ATTN_SMEM ((4 * 64 * ASTR + 192) * (int)sizeof(float))   /* 70400 B */

extern "C" void kernel_launch(void* const* d_in, const int* in_sizes, int n_in,
                              void* d_out, int out_size) {
    const float* x    = (const float*)d_in[0];
    const float* lat  = (const float*)d_in[1];
    const float* g1   = (const float*)d_in[2];
    const float* b1   = (const float*)d_in[3];
    const float* g2   = (const float*)d_in[4];
    const float* b2   = (const float*)d_in[5];
    const float* Wq   = (const float*)d_in[6];
    const float* Wkv  = (const float*)d_in[7];
    const float* Wout = (const float*)d_in[8];
    const int*   um   = (const int*)d_in[9];
    float* out = (float*)d_out;

    cudaFuncSetAttribute(gemm_bf3<G_Q>,   cudaFuncAttributeMaxDynamicSharedMemorySize, GEMM_SMEM);
    cudaFuncSetAttribute(gemm_bf3<G_KV>,  cudaFuncAttributeMaxDynamicSharedMemorySize, GEMM_SMEM);
    cudaFuncSetAttribute(gemm_bf3<G_OUT>, cudaFuncAttributeMaxDynamicSharedMemorySize, GEMM_SMEM);
    cudaFuncSetAttribute(attn_flash,      cudaFuncAttributeMaxDynamicSharedMemorySize, ATTN_SMEM);

    // 1. LayerNorms -> split-bf16 GEMM operands directly
    ln_kernel<<<ROWS_X + ROWS_LAT, 256>>>(x, lat, g1, b1, g2, b2);

    // 2. weight conversions
    convW3<CW_Q><<<dim3(DD / 32, DD / 32), dim3(32, 8)>>>(Wq);
    convW3<CW_KV><<<dim3(2 * DD / 32, DD / 32), dim3(32, 8)>>>(Wkv);
    convW3<CW_OUT><<<dim3(DD / 32, DD / 32), dim3(32, 8)>>>(Wout);

    // 3. Q and KV projections on tensor cores
    gemm_bf3<G_Q><<<dim3(DD / 128, (ROWS_LAT + 127) / 128), 256, GEMM_SMEM>>>(nullptr);
    gemm_bf3<G_KV><<<dim3(2 * DD / 128, ROWS_KV / 128), 256, GEMM_SMEM>>>(nullptr);

    // 4. flash attention (64-key subtiles) + combine; outputs split-bf16
    attn_flash<<<NPART, 256, ATTN_SMEM>>>(um);
    attn_combine<<<dim3(ROWS_LAT, HEADS), 64>>>(um);

    // 5. output projection
    gemm_bf3<G_OUT><<<dim3(DD / 128, (ROWS_LAT + 127) / 128), 256, GEMM_SMEM>>>(out);
}

// round 9
// speedup vs baseline: 3.8378x; 1.2104x over previous
#include <cuda_runtime.h>
#include <cuda_bf16.h>
#include <math.h>
#include <stdint.h>

#define DD 1024
#define HEADS 16
#define DH 64
#define B_LAT 9
#define B_X 8
#define N_KV 256
#define N_Q 64
#define KV_PER_B (N_KV + N_Q)       /* 320  */
#define ROWS_X (B_X * N_KV)         /* 2048 */
#define ROWS_LAT (B_LAT * N_Q)      /* 576  */
#define ROWS_KV (B_X * KV_PER_B)    /* 2560 */
#define EPS 1e-5f
#define NCHUNK 8
#define NPART (B_LAT * HEADS * NCHUNK)   /* 1152 */
#define K3 3072                     /* split-bf16 extended K = 3*1024 */

// ---------------- scratch (static device globals; no allocation) ----------------
__device__ float g_q[ROWS_LAT * DD];
__device__ float g_kv[ROWS_KV * 2 * DD];
__device__ float g_pO[(size_t)NPART * 64 * 64];
__device__ float g_pm[NPART * 64];
__device__ float g_pl[NPART * 64];
// split-bf16 operands: A3 = [Ah | Ah | Al] rows [M,3072]; W3 = [Wh | Wl | Wh] rows [N,3072]
__device__ __nv_bfloat16 g_a3kv[(size_t)ROWS_KV * K3];
__device__ __nv_bfloat16 g_a3small[(size_t)ROWS_LAT * K3];   // lnlat splits, later ao splits
__device__ __nv_bfloat16 g_w3q[(size_t)DD * K3];
__device__ __nv_bfloat16 g_w3kv[(size_t)(2 * DD) * K3];
__device__ __nv_bfloat16 g_w3out[(size_t)DD * K3];

// ---------------- PTX helpers (base ISA only: sm_80-compatible) ----------------
__device__ __forceinline__ uint32_t smem_u32(const void* p) {
    uint32_t a;
    asm("{ .reg .u64 t; cvta.to.shared.u64 t, %1; cvt.u32.u64 %0, t; }" : "=r"(a) : "l"(p));
    return a;
}
__device__ __forceinline__ void cp_async16(uint32_t s, const void* g, int sz) {
    asm volatile("cp.async.cg.shared.global [%0], [%1], 16, %2;"
                 :: "r"(s), "l"(g), "r"(sz) : "memory");
}
#define CP_COMMIT() asm volatile("cp.async.commit_group;" ::: "memory")
#define CP_WAIT0()  asm volatile("cp.async.wait_group 0;" ::: "memory")

__device__ __forceinline__ void ldm_x4(uint32_t* r, uint32_t a) {
    asm volatile("ldmatrix.sync.aligned.m8n8.x4.shared.b16 {%0,%1,%2,%3}, [%4];"
                 : "=r"(r[0]), "=r"(r[1]), "=r"(r[2]), "=r"(r[3]) : "r"(a));
}
__device__ __forceinline__ void mma_bf16(float* d, const uint32_t* a, uint32_t b0, uint32_t b1) {
    asm volatile("mma.sync.aligned.m16n8k16.row.col.f32.bf16.bf16.f32 "
                 "{%0,%1,%2,%3}, {%4,%5,%6,%7}, {%8,%9}, {%0,%1,%2,%3};"
                 : "+f"(d[0]), "+f"(d[1]), "+f"(d[2]), "+f"(d[3])
                 : "r"(a[0]), "r"(a[1]), "r"(a[2]), "r"(a[3]), "r"(b0), "r"(b1));
}

// store 4 fp32 values as split-bf16 triple at dst[0], dst[1024], dst[2048]
__device__ __forceinline__ void store_split4_A(__nv_bfloat16* dst, float4 v) {
    __nv_bfloat16 h0 = __float2bfloat16(v.x), h1 = __float2bfloat16(v.y);
    __nv_bfloat16 h2 = __float2bfloat16(v.z), h3 = __float2bfloat16(v.w);
    __nv_bfloat16 l0 = __float2bfloat16(v.x - __bfloat162float(h0));
    __nv_bfloat16 l1 = __float2bfloat16(v.y - __bfloat162float(h1));
    __nv_bfloat16 l2 = __float2bfloat16(v.z - __bfloat162float(h2));
    __nv_bfloat16 l3 = __float2bfloat16(v.w - __bfloat162float(h3));
    __nv_bfloat162 H0 = {h0, h1}, H1 = {h2, h3}, L0 = {l0, l1}, L1 = {l2, l3};
    *(__nv_bfloat162*)&dst[0]        = H0; *(__nv_bfloat162*)&dst[2]        = H1;
    *(__nv_bfloat162*)&dst[1024]     = H0; *(__nv_bfloat162*)&dst[1026]     = H1;
    *(__nv_bfloat162*)&dst[2048]     = L0; *(__nv_bfloat162*)&dst[2050]     = L1;
}

// ---------------- LayerNorm: one block per row, 256 threads; emits split-bf16 ----------------
__global__ void ln_kernel(const float* __restrict__ x, const float* __restrict__ lat,
                          const float* __restrict__ g1, const float* __restrict__ b1,
                          const float* __restrict__ g2, const float* __restrict__ b2) {
    int row = blockIdx.x;
    const float *src, *g, *b;
    __nv_bfloat16 *dst0, *dst1 = nullptr;
    if (row < ROWS_X) {
        int bb = row / N_KV, n = row % N_KV;
        src = x + (size_t)row * DD; g = g1; b = b1;
        dst0 = g_a3kv + (size_t)(bb * KV_PER_B + n) * K3;
    } else {
        int lr = row - ROWS_X;
        int bb = lr / N_Q, n = lr % N_Q;
        src = lat + (size_t)lr * DD; g = g2; b = b2;
        dst0 = g_a3small + (size_t)lr * K3;
        if (bb < B_X) dst1 = g_a3kv + (size_t)(bb * KV_PER_B + N_KV + n) * K3;
    }
    int tid = threadIdx.x;
    float4 v = ((const float4*)src)[tid];
    float s  = v.x + v.y + v.z + v.w;
    float ss = v.x*v.x + v.y*v.y + v.z*v.z + v.w*v.w;
    #pragma unroll
    for (int o = 16; o; o >>= 1) {
        s  += __shfl_xor_sync(0xFFFFFFFFu, s,  o);
        ss += __shfl_xor_sync(0xFFFFFFFFu, ss, o);
    }
    __shared__ float sb[8], ssb[8];
    int wid = tid >> 5, lane = tid & 31;
    if (lane == 0) { sb[wid] = s; ssb[wid] = ss; }
    __syncthreads();
    float ts = 0.f, tss = 0.f;
    #pragma unroll
    for (int i = 0; i < 8; i++) { ts += sb[i]; tss += ssb[i]; }
    float mean = ts * (1.0f / DD);
    float var  = tss * (1.0f / DD) - mean * mean;
    float inv  = rsqrtf(var + EPS);
    float4 gg = ((const float4*)g)[tid];
    float4 bb4 = ((const float4*)b)[tid];
    float4 o;
    o.x = (v.x - mean) * inv * gg.x + bb4.x;
    o.y = (v.y - mean) * inv * gg.y + bb4.y;
    o.z = (v.z - mean) * inv * gg.z + bb4.z;
    o.w = (v.w - mean) * inv * gg.w + bb4.w;
    store_split4_A(dst0 + tid * 4, o);
    if (dst1) store_split4_A(dst1 + tid * 4, o);
}

// ---------------- merged W conversions: all three weights in one launch ----------------
// tiles of 32x32; Q: 1024 tiles, KV: 2048, OUT: 1024 -> flat grid 4096
__global__ void convW_all(const float* __restrict__ Wq, const float* __restrict__ Wkv,
                          const float* __restrict__ Wout) {
    int t = blockIdx.x;
    const float* W; __nv_bfloat16* dst; int N; int lt;
    if (t < 1024)      { W = Wq;   dst = g_w3q;   N = DD;     lt = t; }
    else if (t < 3072) { W = Wkv;  dst = g_w3kv;  N = 2 * DD; lt = t - 1024; }
    else               { W = Wout; dst = g_w3out; N = DD;     lt = t - 3072; }
    int ntiles_x = N / 32;
    int n0 = (lt % ntiles_x) * 32, k0 = (lt / ntiles_x) * 32;

    __shared__ float tt[32][33];
    int tx = threadIdx.x, ty = threadIdx.y;
    #pragma unroll
    for (int j = 0; j < 4; j++)
        tt[ty + j * 8][tx] = W[(size_t)(k0 + ty + j * 8) * N + n0 + tx];
    __syncthreads();
    #pragma unroll
    for (int j = 0; j < 4; j++) {
        int n = n0 + ty + j * 8, k = k0 + tx;
        float a = tt[tx][ty + j * 8];
        __nv_bfloat16 h = __float2bfloat16(a);
        __nv_bfloat16 l = __float2bfloat16(a - __bfloat162float(h));
        size_t o = (size_t)n * K3 + k;
        dst[o] = h; dst[o + 1024] = l; dst[o + 2048] = h;
    }
}

// ---------------- mma.sync bf16 GEMM core (runtime M/N) ----------------
#define GBK 64
#define KST 72
#define ABUF (128 * KST * 2)
#define STAGE (2 * ABUF)
#define GEMM_SMEM (2 * STAGE)                /* 73728 B */
#define NCH (K3 / GBK)                       /* 48 */

__device__ __forceinline__ void gemm_core(const __nv_bfloat16* __restrict__ A3,
                                          const __nv_bfloat16* __restrict__ B3,
                                          float* __restrict__ C,
                                          int M, int N, int br, int bc,
                                          unsigned char* dynsm) {
    int tid = threadIdx.x, wid = tid >> 5, lane = tid & 31;
    int wm = (wid >> 2) * 64;
    int wn = (wid & 3) * 32;

    auto issue = [&](int kb, int buf) {
        unsigned char* sb = dynsm + buf * STAGE;
        const __nv_bfloat16* Ab = A3 + kb * GBK;
        const __nv_bfloat16* Bb = B3 + (size_t)bc * K3 + kb * GBK;
        #pragma unroll
        for (int j = 0; j < 4; j++) {
            int idx = tid + j * 256;
            int r = idx >> 3, c8 = idx & 7;
            int gr = br + r; int sz = (gr < M) ? 16 : 0;
            if (gr >= M) gr = M - 1;
            cp_async16(smem_u32(sb + (r * KST + c8 * 8) * 2),
                       Ab + (size_t)gr * K3 + c8 * 8, sz);
            cp_async16(smem_u32(sb + ABUF + (r * KST + c8 * 8) * 2),
                       Bb + (size_t)r * K3 + c8 * 8, 16);
        }
        CP_COMMIT();
    };

    float acc[4][4][4] = {};

    issue(0, 0);
    CP_WAIT0();
    __syncthreads();

    for (int kb = 0; kb < NCH; kb++) {
        int cur = kb & 1;
        if (kb + 1 < NCH) issue(kb + 1, cur ^ 1);

        const unsigned char* sA = dynsm + cur * STAGE;
        const unsigned char* sB = sA + ABUF;
        #pragma unroll
        for (int ks = 0; ks < 4; ks++) {
            int k0 = ks * 16;
            uint32_t a[4][4];
            #pragma unroll
            for (int mt = 0; mt < 4; mt++) {
                int arow = wm + mt * 16 + (lane & 15);
                int acol = k0 + (lane >> 4) * 8;
                ldm_x4(a[mt], smem_u32(sA + (arow * KST + acol) * 2));
            }
            uint32_t b[2][4];
            #pragma unroll
            for (int np = 0; np < 2; np++) {
                int nrow = wn + np * 16 + (lane & 7) + ((lane >> 4) << 3);
                int kcol = k0 + ((lane >> 3) & 1) * 8;
                ldm_x4(b[np], smem_u32(sB + (nrow * KST + kcol) * 2));
            }
            #pragma unroll
            for (int mt = 0; mt < 4; mt++)
                #pragma unroll
                for (int nt = 0; nt < 4; nt++)
                    mma_bf16(acc[mt][nt], a[mt], b[nt >> 1][(nt & 1) * 2],
                             b[nt >> 1][(nt & 1) * 2 + 1]);
        }
        if (kb + 1 < NCH) CP_WAIT0();
        __syncthreads();
    }

    #pragma unroll
    for (int mt = 0; mt < 4; mt++) {
        int r0 = br + wm + mt * 16 + (lane >> 2);
        #pragma unroll
        for (int nt = 0; nt < 4; nt++) {
            int c = bc + wn + nt * 8 + (lane & 3) * 2;
            if (r0 < M)
                *(float2*)&C[(size_t)r0 * N + c] = make_float2(acc[mt][nt][0], acc[mt][nt][1]);
            if (r0 + 8 < M)
                *(float2*)&C[(size_t)(r0 + 8) * N + c] = make_float2(acc[mt][nt][2], acc[mt][nt][3]);
        }
    }
}

// merged Q + KV projection: KV tiles (320) first, then Q tiles (40)
#define KV_TILES 320   /* (2048/128) x (2560/128) = 16 x 20 */
#define Q_TILES  40    /* (1024/128) x (576->5 rows) = 8 x 5 */

__global__ __launch_bounds__(256)
void gemm_qkv() {
    extern __shared__ __align__(16) unsigned char dynsm[];
    int bid = blockIdx.x;
    if (bid < KV_TILES) {
        int bx = bid & 15, by = bid >> 4;
        gemm_core(g_a3kv, g_w3kv, g_kv, ROWS_KV, 2 * DD, by * 128, bx * 128, dynsm);
    } else {
        int t = bid - KV_TILES;
        int bx = t & 7, by = t >> 3;
        gemm_core(g_a3small, g_w3q, g_q, ROWS_LAT, DD, by * 128, bx * 128, dynsm);
    }
}

__global__ __launch_bounds__(256)
void gemm_out(float* __restrict__ C) {
    extern __shared__ __align__(16) unsigned char dynsm[];
    gemm_core(g_a3small, g_w3out, C, ROWS_LAT, DD, blockIdx.y * 128, blockIdx.x * 128, dynsm);
}

// ---------------- flash attention: 64-query x 64-key subtiles, split-KV ----------------
#define ASTR 68

__global__ __launch_bounds__(256)
void attn_flash(const int* __restrict__ um_p) {
    int b  = blockIdx.x;
    int qb = b >> 7;
    int h  = (b >> 3) & 15;
    int c  = b & 7;
    int um = *um_p;
    bool single = (um != 0) && (qb < B_X);
    if (single && c != qb) return;   // whole block exits before any barrier

    extern __shared__ float smf[];
    float* Qs = smf;                    // [d][q] pre-scaled
    float* Ks = smf + 64 * ASTR;        // [d][k]
    float* Vs = smf + 2 * 64 * ASTR;    // [k][d]
    float* Ps = smf + 3 * 64 * ASTR;    // [q][k]
    float* mrow = smf + 4 * 64 * ASTR;
    float* lrow = mrow + 64;
    float* arow = mrow + 128;

    int tid = threadIdx.x;
    int ty = tid >> 4, tx = tid & 15;

    #pragma unroll
    for (int it = 0; it < 4; it++) {
        int row = ty + it * 16;
        int col = tx * 4;
        float4 v = *(const float4*)&g_q[(size_t)(qb * 64 + row) * DD + h * DH + col];
        Qs[(col + 0) * ASTR + row] = v.x * 0.125f;
        Qs[(col + 1) * ASTR + row] = v.y * 0.125f;
        Qs[(col + 2) * ASTR + row] = v.z * 0.125f;
        Qs[(col + 3) * ASTR + row] = v.w * 0.125f;
    }
    if (tid < 64) { mrow[tid] = -INFINITY; lrow[tid] = 0.f; }

    float oacc[4][4] = {};
    int ks0 = c * KV_PER_B;

    for (int sub = 0; sub < 5; sub++) {
        int kb = ks0 + sub * 64;
        __syncthreads();
        #pragma unroll
        for (int it = 0; it < 4; it++) {
            int row = ty + it * 16;
            int col = tx * 4;
            const float* base = g_kv + (size_t)(kb + row) * (2 * DD) + h * DH + col;
            float4 kk = *(const float4*)base;
            Ks[(col + 0) * ASTR + row] = kk.x;
            Ks[(col + 1) * ASTR + row] = kk.y;
            Ks[(col + 2) * ASTR + row] = kk.z;
            Ks[(col + 3) * ASTR + row] = kk.w;
            *(float4*)&Vs[row * ASTR + col] = *(const float4*)(base + DD);
        }
        __syncthreads();

        float sacc[4][4] = {};
        #pragma unroll
        for (int d = 0; d < 64; d++) {
            float4 aq = *(const float4*)&Qs[d * ASTR + ty * 4];
            float4 bk = *(const float4*)&Ks[d * ASTR + tx * 4];
            sacc[0][0] += aq.x * bk.x; sacc[0][1] += aq.x * bk.y;
            sacc[0][2] += aq.x * bk.z; sacc[0][3] += aq.x * bk.w;
            sacc[1][0] += aq.y * bk.x; sacc[1][1] += aq.y * bk.y;
            sacc[1][2] += aq.y * bk.z; sacc[1][3] += aq.y * bk.w;
            sacc[2][0] += aq.z * bk.x; sacc[2][1] += aq.z * bk.y;
            sacc[2][2] += aq.z * bk.z; sacc[2][3] += aq.z * bk.w;
            sacc[3][0] += aq.w * bk.x; sacc[3][1] += aq.w * bk.y;
            sacc[3][2] += aq.w * bk.z; sacc[3][3] += aq.w * bk.w;
        }
        #pragma unroll
        for (int i = 0; i < 4; i++)
            #pragma unroll
            for (int j = 0; j < 4; j++)
                Ps[(ty * 4 + i) * ASTR + tx * 4 + j] = sacc[i][j];
        __syncthreads();

        {
            int r = tid >> 2, part = tid & 3;
            float rm = -INFINITY;
            #pragma unroll
            for (int i = 0; i < 16; i++)
                rm = fmaxf(rm, Ps[r * ASTR + part * 16 + i]);
            rm = fmaxf(rm, __shfl_xor_sync(0xFFFFFFFFu, rm, 1));
            rm = fmaxf(rm, __shfl_xor_sync(0xFFFFFFFFu, rm, 2));
            float mo = mrow[r];
            float nm = fmaxf(mo, rm);
            float psum = 0.f;
            #pragma unroll
            for (int i = 0; i < 16; i++) {
                float p = __expf(Ps[r * ASTR + part * 16 + i] - nm);
                Ps[r * ASTR + part * 16 + i] = p;
                psum += p;
            }
            psum += __shfl_xor_sync(0xFFFFFFFFu, psum, 1);
            psum += __shfl_xor_sync(0xFFFFFFFFu, psum, 2);
            if (part == 0) {
                float a = __expf(mo - nm);
                arow[r] = a;
                lrow[r] = lrow[r] * a + psum;
                mrow[r] = nm;
            }
        }
        __syncthreads();

        float al[4];
        #pragma unroll
        for (int i = 0; i < 4; i++) al[i] = arow[ty * 4 + i];
        #pragma unroll
        for (int i = 0; i < 4; i++)
            #pragma unroll
            for (int j = 0; j < 4; j++) oacc[i][j] *= al[i];
        #pragma unroll
        for (int k = 0; k < 64; k++) {
            float4 v4 = *(const float4*)&Vs[k * ASTR + tx * 4];
            float p0 = Ps[(ty * 4 + 0) * ASTR + k];
            float p1 = Ps[(ty * 4 + 1) * ASTR + k];
            float p2 = Ps[(ty * 4 + 2) * ASTR + k];
            float p3 = Ps[(ty * 4 + 3) * ASTR + k];
            oacc[0][0] += p0 * v4.x; oacc[0][1] += p0 * v4.y;
            oacc[0][2] += p0 * v4.z; oacc[0][3] += p0 * v4.w;
            oacc[1][0] += p1 * v4.x; oacc[1][1] += p1 * v4.y;
            oacc[1][2] += p1 * v4.z; oacc[1][3] += p1 * v4.w;
            oacc[2][0] += p2 * v4.x; oacc[2][1] += p2 * v4.y;
            oacc[2][2] += p2 * v4.z; oacc[2][3] += p2 * v4.w;
            oacc[3][0] += p3 * v4.x; oacc[3][1] += p3 * v4.y;
            oacc[3][2] += p3 * v4.z; oacc[3][3] += p3 * v4.w;
        }
    }

    if (single) {
        #pragma unroll
        for (int i = 0; i < 4; i++) {
            float inv = 1.0f / lrow[ty * 4 + i];
            float4 o = make_float4(oacc[i][0] * inv, oacc[i][1] * inv,
                                   oacc[i][2] * inv, oacc[i][3] * inv);
            store_split4_A(g_a3small + (size_t)(qb * 64 + ty * 4 + i) * K3 + h * DH + tx * 4, o);
        }
    } else {
        int pidx = (qb * HEADS + h) * NCHUNK + c;
        #pragma unroll
        for (int i = 0; i < 4; i++) {
            float4 o = make_float4(oacc[i][0], oacc[i][1], oacc[i][2], oacc[i][3]);
            *(float4*)&g_pO[((size_t)pidx * 64 + ty * 4 + i) * 64 + tx * 4] = o;
        }
        if (tid < 64) {
            g_pm[pidx * 64 + tid] = mrow[tid];
            g_pl[pidx * 64 + tid] = lrow[tid];
        }
    }
}

// merge 8 split-KV partials; coarsened: 256 threads = 4 (q,h) pairs per block
__global__ __launch_bounds__(256)
void attn_combine(const int* __restrict__ um_p) {
    int q = blockIdx.x * 4 + (threadIdx.x >> 6);
    int h = blockIdx.y;
    int qb = q >> 6, qq = q & 63;
    int um = *um_p;
    if (um && qb < B_X) return;   // uniform across block (4 consecutive q share qb)
    int d = threadIdx.x & 63;
    int pbase = (qb * HEADS + h) * NCHUNK;
    float mv[NCHUNK], lv[NCHUNK];
    float M = -INFINITY;
    #pragma unroll
    for (int c = 0; c < NCHUNK; c++) {
        mv[c] = g_pm[(pbase + c) * 64 + qq];
        lv[c] = g_pl[(pbase + c) * 64 + qq];
        M = fmaxf(M, mv[c]);
    }
    float L = 0.f, o = 0.f;
    #pragma unroll
    for (int c = 0; c < NCHUNK; c++) {
        float e = __expf(mv[c] - M);
        L += lv[c] * e;
        o += g_pO[((size_t)(pbase + c) * 64 + qq) * 64 + d] * e;
    }
    float r = o / L;
    __nv_bfloat16 hh = __float2bfloat16(r);
    __nv_bfloat16 ll = __float2bfloat16(r - __bfloat162float(hh));
    __nv_bfloat16* dst = g_a3small + (size_t)q * K3 + h * DH + d;
    dst[0] = hh; dst[1024] = hh; dst[2048] = ll;
}

// ---------------- launch ----------------
#define ATTN_SMEM ((4 * 64 * ASTR + 192) * (int)sizeof(float))   /* 70400 B */

extern "C" void kernel_launch(void* const* d_in, const int* in_sizes, int n_in,
                              void* d_out, int out_size) {
    const float* x    = (const float*)d_in[0];
    const float* lat  = (const float*)d_in[1];
    const float* g1   = (const float*)d_in[2];
    const float* b1   = (const float*)d_in[3];
    const float* g2   = (const float*)d_in[4];
    const float* b2   = (const float*)d_in[5];
    const float* Wq   = (const float*)d_in[6];
    const float* Wkv  = (const float*)d_in[7];
    const float* Wout = (const float*)d_in[8];
    const int*   um   = (const int*)d_in[9];
    float* out = (float*)d_out;

    cudaFuncSetAttribute(gemm_qkv,   cudaFuncAttributeMaxDynamicSharedMemorySize, GEMM_SMEM);
    cudaFuncSetAttribute(gemm_out,   cudaFuncAttributeMaxDynamicSharedMemorySize, GEMM_SMEM);
    cudaFuncSetAttribute(attn_flash, cudaFuncAttributeMaxDynamicSharedMemorySize, ATTN_SMEM);

    // 1. LayerNorms -> split-bf16 GEMM operands directly
    ln_kernel<<<ROWS_X + ROWS_LAT, 256>>>(x, lat, g1, b1, g2, b2);

    // 2. all weight conversions, one launch
    convW_all<<<4096, dim3(32, 8)>>>(Wq, Wkv, Wout);

    // 3. Q + KV projections, one launch (Q tiles backfill the KV tail wave)
    gemm_qkv<<<KV_TILES + Q_TILES, 256, GEMM_SMEM>>>();

    // 4. flash attention (64-key subtiles) + coarsened combine; outputs split-bf16
    attn_flash<<<NPART, 256, ATTN_SMEM>>>(um);
    attn_combine<<<dim3(ROWS_LAT / 4, HEADS), 256>>>(um);

    // 5. output projection
    gemm_out<<<dim3(DD / 128, (ROWS_LAT + 127) / 128), 256, GEMM_SMEM>>>(out);
}